// round 7
// baseline (speedup 1.0000x reference)
#include <cuda_runtime.h>
#include <cstdint>

#define B    32768
#define DIN  4096
#define H    100
#define DOUT 1000
#define BN_EPS 1e-4f

#define KC      64
#define NCHUNK  (DIN / KC)          // 64
#define NPAD    128

// smem geometry: int8 digit planes, 128 rows x 64B, pitch 80 (conflict-free ldsm)
#define PITCH_A   80
#define PLANE_SZ  (128 * PITCH_A)   // 10240
#define B_OFF     (3 * PLANE_SZ)    // 30720
#define B_SZ      (56 * PITCH_A)    // 4480
#define BUF_SZ    (B_OFF + B_SZ)    // 35200
#define SB1_OFF   (2 * BUF_SZ)      // 70400
#define SMEM_TOTAL (2 * BUF_SZ + 512)

// ---- scratch ----
__device__ float     g_h[(size_t)B * H];
__device__ float     g_scale[H];
__device__ float     g_shift[H];
__device__ unsigned  g_w2p[DOUT * 4];
__device__ signed char g_w1s[(size_t)NPAD * DIN];  // sign(W1) int8, rows 100..127 = 0
__device__ float     g_part[256 * 200];            // per-rowblock BN partials

// ============================================================
// helpers
// ============================================================
__device__ __forceinline__ uint32_t smem_u32(const void* p) {
    uint32_t a;
    asm("{ .reg .u64 t; cvta.to.shared.u64 t, %1; cvt.u32.u64 %0, t; }"
        : "=r"(a) : "l"(p));
    return a;
}
__device__ __forceinline__ void ldsm4(uint32_t* r, uint32_t addr) {
    asm volatile("ldmatrix.sync.aligned.m8n8.x4.shared.b16 {%0,%1,%2,%3}, [%4];"
                 : "=r"(r[0]), "=r"(r[1]), "=r"(r[2]), "=r"(r[3]) : "r"(addr));
}
__device__ __forceinline__ void ldsm2(uint32_t* r, uint32_t addr) {
    asm volatile("ldmatrix.sync.aligned.m8n8.x2.shared.b16 {%0,%1}, [%2];"
                 : "=r"(r[0]), "=r"(r[1]) : "r"(addr));
}
__device__ __forceinline__ void mma_s8(int* d, const uint32_t* a,
                                       const uint32_t* b) {
    asm volatile(
        "mma.sync.aligned.m16n8k32.row.col.s32.s8.s8.s32 "
        "{%0,%1,%2,%3}, {%4,%5,%6,%7}, {%8,%9}, {%0,%1,%2,%3};"
        : "+r"(d[0]), "+r"(d[1]), "+r"(d[2]), "+r"(d[3])
        : "r"(a[0]), "r"(a[1]), "r"(a[2]), "r"(a[3]), "r"(b[0]), "r"(b[1]));
}
__device__ __forceinline__ uint32_t pack4b(int a, int b, int c, int d) {
    return (uint32_t)(a & 255) | ((uint32_t)(b & 255) << 8) |
           ((uint32_t)(c & 255) << 16) | ((uint32_t)(d & 255) << 24);
}
// exact 3-digit decomposition of rn(x * 2^20)
__device__ __forceinline__ void dig3(float xf, int& d0, int& d1, int& d2) {
    xf = fminf(7.8f, fmaxf(-7.8f, xf));
    int v  = __float2int_rn(xf * 1048576.0f);
    d2 = (v << 24) >> 24;
    int v1 = (v - d2) >> 8;
    d1 = (v1 << 24) >> 24;
    d0 = (v1 - d1) >> 8;
}
__device__ __forceinline__ void conv_store(char* base, int idx,
                                           float4 va, float4 vb) {
    int r = idx >> 3, p = idx & 7;
    float e[8] = {va.x, va.y, va.z, va.w, vb.x, vb.y, vb.z, vb.w};
    int d0[8], d1[8], d2[8];
    #pragma unroll
    for (int k = 0; k < 8; k++) dig3(e[k], d0[k], d1[k], d2[k]);
    char* p0 = base + r * PITCH_A + p * 8;
    *(uint2*)(p0) = make_uint2(pack4b(d0[0], d0[1], d0[2], d0[3]),
                               pack4b(d0[4], d0[5], d0[6], d0[7]));
    *(uint2*)(p0 + PLANE_SZ) = make_uint2(pack4b(d1[0], d1[1], d1[2], d1[3]),
                                          pack4b(d1[4], d1[5], d1[6], d1[7]));
    *(uint2*)(p0 + 2 * PLANE_SZ) = make_uint2(pack4b(d2[0], d2[1], d2[2], d2[3]),
                                              pack4b(d2[4], d2[5], d2[6], d2[7]));
}

// ============================================================
// Kernel P: pack sign(W1)->int8 and sign(W2)->bitmask
// ============================================================
__global__ void pack_all(const float* __restrict__ W1,
                         const float* __restrict__ W2) {
    int gb = blockIdx.x, tid = threadIdx.x;
    if (gb < 512) {
        int ib  = (gb * 256 + tid) * 4;       // byte index into g_w1s
        int row = ib >> 12, col = ib & 4095;
        char4 o = make_char4(0, 0, 0, 0);
        if (row < H) {
            float4 v = *(const float4*)(W1 + (size_t)row * DIN + col);
            o.x = (v.x >= 0.f) ? 1 : -1;
            o.y = (v.y >= 0.f) ? 1 : -1;
            o.z = (v.z >= 0.f) ? 1 : -1;
            o.w = (v.w >= 0.f) ? 1 : -1;
        }
        *(char4*)((char*)g_w1s + ib) = o;
    } else {
        int j = (gb - 512) * 256 + tid;
        if (j >= DOUT) return;
        unsigned w0 = 0, w1 = 0, w2 = 0, w3 = 0;
        const float* r = W2 + (size_t)j * H;
        #pragma unroll 4
        for (int k = 0; k < 32; k++)  if (r[k]      >= 0.f) w0 |= (1u << k);
        #pragma unroll 4
        for (int k = 0; k < 32; k++)  if (r[32 + k] >= 0.f) w1 |= (1u << k);
        #pragma unroll 4
        for (int k = 0; k < 32; k++)  if (r[64 + k] >= 0.f) w2 |= (1u << k);
        #pragma unroll
        for (int k = 0; k < 4;  k++)  if (r[96 + k] >= 0.f) w3 |= (1u << k);
        g_w2p[j * 4 + 0] = w0; g_w2p[j * 4 + 1] = w1;
        g_w2p[j * 4 + 2] = w2; g_w2p[j * 4 + 3] = w3;
    }
}

// ============================================================
// GEMM1 body: int8 3-digit MMA, M=128 x N=8*NGR per CTA.
// ============================================================
template<int NGR>
__device__ __forceinline__ void gemm_body(
    const float* __restrict__ x, const float* __restrict__ b1,
    char* smem, int row0, int wbase, int rb) {

    const uint32_t sm_base = smem_u32(smem);
    const int tid  = threadIdx.x;
    const int warp = tid >> 5;
    const int lane = tid & 31;
    const int fbase = (NGR == 6) ? 56 : 0;

    float* sb1 = (float*)(smem + SB1_OFF);
    if (tid < H) sb1[tid] = b1[tid];

    // ---- stage chunk 0 ----
    {
        const float* xp = x + (size_t)row0 * DIN;
        #pragma unroll
        for (int i = 0; i < 4; i++) {
            int idx = tid + i * 256;               // pair index < 1024
            int r = idx >> 3, p = idx & 7;
            float4 va = __ldg((const float4*)(xp + (size_t)r * DIN + p * 8));
            float4 vb = __ldg((const float4*)(xp + (size_t)r * DIN + p * 8 + 4));
            conv_store(smem, idx, va, vb);
        }
        if (tid < NGR * 32) {
            int r = tid >> 2, q = tid & 3;
            uint4 v = __ldg((const uint4*)((const char*)g_w1s +
                           (size_t)(wbase + r) * DIN + q * 16));
            *(uint4*)(smem + B_OFF + r * PITCH_A + q * 16) = v;
        }
    }
    __syncthreads();

    int acc0[NGR * 4], acc1[NGR * 4], acc2[NGR * 4];
    #pragma unroll
    for (int i = 0; i < NGR * 4; i++) { acc0[i] = 0; acc1[i] = 0; acc2[i] = 0; }

    const uint32_t a_loff = (uint32_t)((warp * 16 + (lane & 15)) * PITCH_A +
                                       (lane >> 4) * 16);
    const uint32_t b_loff = (uint32_t)(((lane & 15)) * PITCH_A + (lane >> 4) * 16);
    const uint32_t b2_loff = (uint32_t)((48 + (lane & 7)) * PITCH_A +
                                        ((lane >> 3) & 1) * 16);

    for (int c = 0; c < NCHUNK; c++) {
        const int buf = c & 1;
        const uint32_t abase = sm_base + buf * BUF_SZ;

        // ---- prefetch chunk c+1 ----
        float4 xva[4], xvb[4]; uint4 wv;
        if (c < NCHUNK - 1) {
            const float* xp = x + (size_t)row0 * DIN + (c + 1) * KC;
            #pragma unroll
            for (int i = 0; i < 4; i++) {
                int idx = tid + i * 256;
                int r = idx >> 3, p = idx & 7;
                xva[i] = __ldg((const float4*)(xp + (size_t)r * DIN + p * 8));
                xvb[i] = __ldg((const float4*)(xp + (size_t)r * DIN + p * 8 + 4));
            }
            if (tid < NGR * 32) {
                int r = tid >> 2, q = tid & 3;
                wv = __ldg((const uint4*)((const char*)g_w1s +
                          (size_t)(wbase + r) * DIN + (c + 1) * 64 + q * 16));
            }
        }

        // ---- compute chunk c ----
        #pragma unroll
        for (int ks = 0; ks < 2; ks++) {
            uint32_t bf[NGR * 2];
            #pragma unroll
            for (int j = 0; j < 3; j++) {
                uint32_t t4[4];
                ldsm4(t4, abase + B_OFF + (uint32_t)(j * 16 * PITCH_A) +
                      b_loff + ks * 32);
                bf[4 * j + 0] = t4[0]; bf[4 * j + 1] = t4[2];
                bf[4 * j + 2] = t4[1]; bf[4 * j + 3] = t4[3];
            }
            if (NGR == 7) {
                uint32_t t2[2];
                ldsm2(t2, abase + B_OFF + b2_loff + ks * 32);
                bf[12] = t2[0]; bf[13] = t2[1];
            }
            #pragma unroll
            for (int pd = 0; pd < 3; pd++) {
                uint32_t a4[4];
                ldsm4(a4, abase + pd * PLANE_SZ + a_loff + ks * 32);
                int* acc = (pd == 0) ? acc0 : (pd == 1) ? acc1 : acc2;
                #pragma unroll
                for (int g = 0; g < NGR; g++)
                    mma_s8(acc + 4 * g, a4, bf + 2 * g);
            }
        }

        __syncthreads();

        // ---- convert + STS chunk c+1 ----
        if (c < NCHUNK - 1) {
            char* base = smem + (buf ^ 1) * BUF_SZ;
            #pragma unroll
            for (int i = 0; i < 4; i++)
                conv_store(base, tid + i * 256, xva[i], xvb[i]);
            if (tid < NGR * 32) {
                int r = tid >> 2, q = tid & 3;
                *(uint4*)(base + B_OFF + r * PITCH_A + q * 16) = wv;
            }
        }
        __syncthreads();
    }

    // ---- epilogue ----
    const float INVS = 1.0f / 1048576.0f;
    const int gr = row0 + warp * 16 + (lane >> 2);
    const int cb = (lane & 3) * 2;
    #pragma unroll
    for (int g = 0; g < NGR; g++) {
        int c0 = fbase + g * 8 + cb;
        if (c0 < H) {
            long long v0 = (((long long)acc0[4*g+0]) << 16) + (acc1[4*g+0] << 8) + acc2[4*g+0];
            long long v1 = (((long long)acc0[4*g+1]) << 16) + (acc1[4*g+1] << 8) + acc2[4*g+1];
            long long v2 = (((long long)acc0[4*g+2]) << 16) + (acc1[4*g+2] << 8) + acc2[4*g+2];
            long long v3 = (((long long)acc0[4*g+3]) << 16) + (acc1[4*g+3] << 8) + acc2[4*g+3];
            float2 lo, hi;
            lo.x = (float)v0 * INVS + sb1[c0];
            lo.y = (float)v1 * INVS + sb1[c0 + 1];
            hi.x = (float)v2 * INVS + sb1[c0];
            hi.y = (float)v3 * INVS + sb1[c0 + 1];
            *(float2*)(g_h + (size_t)gr * H + c0)       = lo;
            *(float2*)(g_h + (size_t)(gr + 8) * H + c0) = hi;
        }
    }

    // ---- fused BN pass 1 (this CTA's feature columns only) ----
    __syncthreads();
    const int nf = (NGR == 6) ? 44 : 56;
    float s = 0.f, s2 = 0.f;
    if (tid < 2 * nf) {
        int fl = tid % nf, st = tid / nf;
        const float* hp = g_h + (size_t)row0 * H + fbase + fl;
        for (int rr = st; rr < 128; rr += 2) {
            float v = hp[(size_t)rr * H];
            s += v;
            s2 = fmaf(v, v, s2);
        }
    }
    float* red = (float*)smem;
    if (tid < 2 * nf) { red[tid] = s; red[224 + tid] = s2; }
    __syncthreads();
    if (tid < nf) {
        g_part[rb * 200 + fbase + tid]       = red[tid] + red[tid + nf];
        g_part[rb * 200 + 100 + fbase + tid] = red[224 + tid] + red[224 + tid + nf];
    }
}

__global__ void __launch_bounds__(256, 1)
gemm1_i8(const float* __restrict__ x, const float* __restrict__ b1) {
    extern __shared__ char smem[];
    int bid = blockIdx.x;
    int rb = bid >> 1;
    if (bid & 1) gemm_body<6>(x, b1, smem, rb * 128, 56, rb);
    else         gemm_body<7>(x, b1, smem, rb * 128, 0,  rb);
}

// ============================================================
// Kernel S: finish batch-norm (one warp per feature)
// ============================================================
__global__ void bn_finish(const float* __restrict__ gamma,
                          const float* __restrict__ beta) {
    int f = blockIdx.x;
    int lane = threadIdx.x;
    float s = 0.f, s2 = 0.f;
    for (int c = lane; c < 256; c += 32) {
        s  += g_part[c * 200 + f];
        s2 += g_part[c * 200 + 100 + f];
    }
    #pragma unroll
    for (int off = 16; off > 0; off >>= 1) {
        s  += __shfl_xor_sync(0xffffffffu, s,  off);
        s2 += __shfl_xor_sync(0xffffffffu, s2, off);
    }
    if (lane == 0) {
        float mu  = s  * (1.f / B);
        float m2  = s2 * (1.f / B);
        float var = m2 - mu * mu;
        float sc  = gamma[f] * rsqrtf(var + BN_EPS);
        g_scale[f] = sc;
        g_shift[f] = fmaf(-mu, sc, beta[f]);
    }
}

// ============================================================
// Kernel H: head — one row/warp, popc GEMM2 + log_softmax
// ============================================================
__global__ __launch_bounds__(256)
void head(const float* __restrict__ b2, float* __restrict__ out) {
    __shared__ unsigned sw[DOUT * 4];
    __shared__ float    sb[DOUT];
    __shared__ float    ssc[H], ssh[H];

    const int tid = threadIdx.x;
    for (int i = tid; i < DOUT * 4; i += 256) sw[i] = g_w2p[i];
    for (int i = tid; i < DOUT;     i += 256) sb[i] = b2[i];
    if (tid < H) { ssc[tid] = g_scale[tid]; ssh[tid] = g_shift[tid]; }
    __syncthreads();

    const int lane = tid & 31;
    const int warp = tid >> 5;
    const int row  = blockIdx.x * 8 + warp;

    const float* hr = g_h + (size_t)row * H;
    bool p0 = fmaf(hr[lane],      ssc[lane],      ssh[lane])      >= 0.f;
    bool p1 = fmaf(hr[32 + lane], ssc[32 + lane], ssh[32 + lane]) >= 0.f;
    bool p2 = fmaf(hr[64 + lane], ssc[64 + lane], ssh[64 + lane]) >= 0.f;
    bool p3 = (lane < 4) ?
              (fmaf(hr[96 + lane], ssc[96 + lane], ssh[96 + lane]) >= 0.f) : false;
    unsigned a0 = __ballot_sync(0xffffffffu, p0);
    unsigned a1 = __ballot_sync(0xffffffffu, p1);
    unsigned a2 = __ballot_sync(0xffffffffu, p2);
    unsigned a3 = __ballot_sync(0xffffffffu, p3);

    float o[32];
    float mx = -1e30f;
    #pragma unroll
    for (int i = 0; i < 32; i++) {
        int j = i * 32 + lane;
        if (j < DOUT) {
            uint4 w = *(const uint4*)&sw[j * 4];
            int p = __popc(a0 ^ w.x) + __popc(a1 ^ w.y) +
                    __popc(a2 ^ w.z) + __popc(a3 ^ w.w);
            o[i] = (float)(H - 2 * p) + sb[j];
            mx = fmaxf(mx, o[i]);
        } else {
            o[i] = -1e30f;
        }
    }
    #pragma unroll
    for (int off = 16; off > 0; off >>= 1)
        mx = fmaxf(mx, __shfl_xor_sync(0xffffffffu, mx, off));

    float s = 0.f;
    #pragma unroll
    for (int i = 0; i < 32; i++)
        s += exp2f((o[i] - mx) * 1.4426950408889634f);
    #pragma unroll
    for (int off = 16; off > 0; off >>= 1)
        s += __shfl_xor_sync(0xffffffffu, s, off);

    float lse = fmaf(0.69314718055994531f, __log2f(s), mx);

    float* orow = out + (size_t)row * DOUT;
    #pragma unroll
    for (int i = 0; i < 32; i++) {
        int j = i * 32 + lane;
        if (j < DOUT) orow[j] = o[i] - lse;
    }
}

// ============================================================
// Launch
// ============================================================
extern "C" void kernel_launch(void* const* d_in, const int* in_sizes, int n_in,
                              void* d_out, int out_size) {
    (void)in_sizes; (void)n_in; (void)out_size;
    const float* x     = (const float*)d_in[0];
    const float* W1    = (const float*)d_in[1];
    const float* b1    = (const float*)d_in[2];
    const float* gamma = (const float*)d_in[3];
    const float* beta  = (const float*)d_in[4];
    const float* W2    = (const float*)d_in[5];
    const float* b2    = (const float*)d_in[6];
    float* out = (float*)d_out;

    static int smem_set = 0;
    if (!smem_set) {
        cudaFuncSetAttribute(gemm1_i8, cudaFuncAttributeMaxDynamicSharedMemorySize,
                             SMEM_TOTAL);
        smem_set = 1;
    }

    pack_all<<<516, 256>>>(W1, W2);
    gemm1_i8<<<B / 64, 256, SMEM_TOTAL>>>(x, b1);
    bn_finish<<<H, 32>>>(gamma, beta);
    head<<<B / 8, 256>>>(b2, out);
}

// round 8
// speedup vs baseline: 2.3123x; 2.3123x over previous
#include <cuda_runtime.h>
#include <cuda_fp16.h>
#include <cstdint>

#define B    32768
#define DIN  4096
#define H    100
#define DOUT 1000
#define BN_EPS 1e-4f

#define KC      64                 // K per chunk
#define NCHUNK  (DIN / KC)         // 64
#define NPAD    128                // padded feature rows in g_w1h
#define NG      13                 // n8 groups (N=104 >= 100)

// padded smem tile geometry (fp16: 64 elems = 128B + 16B pad)
#define PITCH_B   144
#define SPLIT_SZ  (128 * PITCH_B)  // 18432
#define BUF_SZ    (3 * SPLIT_SZ)   // A-hi, A-lo, B = 55296
#define B_OFF     (2 * SPLIT_SZ)
#define SB1_OFF   (2 * BUF_SZ)     // b1 staging
#define SMEM_TOTAL (2 * BUF_SZ + 512)

// ---- scratch (no allocations allowed) ----
__device__ float     g_h[(size_t)B * H];
__device__ float     g_scale[H];
__device__ float     g_shift[H];
__device__ unsigned  g_w2p[DOUT * 4];
__device__ __half    g_w1h[(size_t)NPAD * DIN];  // sign(W1) fp16, rows 100..127 = 0
__device__ float     g_part[256 * 200];          // per-CTA BN partials [s|s2]

// ============================================================
// helpers
// ============================================================
__device__ __forceinline__ uint32_t smem_u32(const void* p) {
    uint32_t a;
    asm("{ .reg .u64 t; cvta.to.shared.u64 t, %1; cvt.u32.u64 %0, t; }"
        : "=r"(a) : "l"(p));
    return a;
}
__device__ __forceinline__ void ldsm4(uint32_t* r, uint32_t addr) {
    asm volatile("ldmatrix.sync.aligned.m8n8.x4.shared.b16 {%0,%1,%2,%3}, [%4];"
                 : "=r"(r[0]), "=r"(r[1]), "=r"(r[2]), "=r"(r[3]) : "r"(addr));
}
__device__ __forceinline__ void ldsm2(uint32_t* r, uint32_t addr) {
    asm volatile("ldmatrix.sync.aligned.m8n8.x2.shared.b16 {%0,%1}, [%2];"
                 : "=r"(r[0]), "=r"(r[1]) : "r"(addr));
}
__device__ __forceinline__ void mma16816(float* d, const uint32_t* a,
                                         const uint32_t* b) {
    asm volatile(
        "mma.sync.aligned.m16n8k16.row.col.f32.f16.f16.f32 "
        "{%0,%1,%2,%3}, {%4,%5,%6,%7}, {%8,%9}, {%0,%1,%2,%3};"
        : "+f"(d[0]), "+f"(d[1]), "+f"(d[2]), "+f"(d[3])
        : "r"(a[0]), "r"(a[1]), "r"(a[2]), "r"(a[3]), "r"(b[0]), "r"(b[1]));
}
__device__ __forceinline__ void cp16(uint32_t saddr, const void* g) {
    asm volatile("cp.async.cg.shared.global [%0], [%1], 16;"
                 :: "r"(saddr), "l"(g) : "memory");
}
#define CP_COMMIT() asm volatile("cp.async.commit_group;" ::: "memory")
#define CP_WAIT0()  asm volatile("cp.async.wait_group 0;"  ::: "memory")

// exact 2-way fp16 split
__device__ __forceinline__ void split2(float4 v, uint2& hi, uint2& lo) {
    __half2 a = __floats2half2_rn(v.x, v.y);
    __half2 b = __floats2half2_rn(v.z, v.w);
    float2 fa = __half22float2(a), fb = __half22float2(b);
    __half2 c = __floats2half2_rn(v.x - fa.x, v.y - fa.y);
    __half2 d = __floats2half2_rn(v.z - fb.x, v.w - fb.y);
    hi = make_uint2(*(uint32_t*)&a, *(uint32_t*)&b);
    lo = make_uint2(*(uint32_t*)&c, *(uint32_t*)&d);
}

// ============================================================
// Kernel P: fused packing of sign(W1)->fp16 and sign(W2)->bitmask
// ============================================================
__global__ void pack_all(const float* __restrict__ W1,
                         const float* __restrict__ W2) {
    int gb = blockIdx.x;
    int tid = threadIdx.x;
    if (gb < 2048) {
        int idx = gb * 256 + tid;
        int row = idx >> 12;
        int col = idx & 4095;
        float v = 0.f;
        if (row < H) v = (W1[(size_t)row * DIN + col] >= 0.f) ? 1.f : -1.f;
        g_w1h[(size_t)row * DIN + col] = __float2half(v);
    } else {
        int j = (gb - 2048) * 256 + tid;
        if (j >= DOUT) return;
        unsigned w0 = 0, w1 = 0, w2 = 0, w3 = 0;
        const float* r = W2 + (size_t)j * H;
        #pragma unroll 4
        for (int k = 0; k < 32; k++)  if (r[k]      >= 0.f) w0 |= (1u << k);
        #pragma unroll 4
        for (int k = 0; k < 32; k++)  if (r[32 + k] >= 0.f) w1 |= (1u << k);
        #pragma unroll 4
        for (int k = 0; k < 32; k++)  if (r[64 + k] >= 0.f) w2 |= (1u << k);
        #pragma unroll
        for (int k = 0; k < 4;  k++)  if (r[96 + k] >= 0.f) w3 |= (1u << k);
        g_w2p[j * 4 + 0] = w0; g_w2p[j * 4 + 1] = w1;
        g_w2p[j * 4 + 2] = w2; g_w2p[j * 4 + 3] = w3;
    }
}

// ============================================================
// Kernel G: gemm1 via mma.sync fp16 2-split, 256 threads,
// cp.async B tile, single sync per chunk, fused BN partials.
// ============================================================
__global__ void __launch_bounds__(256, 1)
gemm1_mma(const float* __restrict__ x, const float* __restrict__ b1) {
    extern __shared__ char smem[];
    const uint32_t sm_base = smem_u32(smem);
    const int tid  = threadIdx.x;
    const int warp = tid >> 5;
    const int lane = tid & 31;
    const int row0 = blockIdx.x * 128;

    // B-tile cp.async source/dest for this thread (4 x 16B per chunk)
    const int br = tid >> 1;                  // row pairs: rows br, br+128? no:
    // 128 rows x 8 uint4 = 1024 ops; thread does rows (tid>>1), cols...
    // simpler: op index = tid + i*256; r = idx>>3, q = idx&7
    float* sb1 = (float*)(smem + SB1_OFF);
    if (tid < 104) sb1[tid] = (tid < H) ? b1[tid] : 0.f;
    (void)br;

    // ---- stage chunk 0 into buf 0 ----
    {
        // B via cp.async
        #pragma unroll
        for (int i = 0; i < 4; i++) {
            int idx = tid + i * 256;
            int r = idx >> 3, q = idx & 7;
            cp16(sm_base + B_OFF + (uint32_t)(r * PITCH_B + q * 16),
                 (const char*)g_w1h + (size_t)r * (DIN * 2) + q * 16);
        }
        CP_COMMIT();
        // x convert + STS
        const float* xp = x + (size_t)row0 * DIN;
        #pragma unroll
        for (int i = 0; i < 8; i++) {
            int idx = tid + i * 256;
            int r = idx >> 4, q = idx & 15;
            float4 v = __ldg((const float4*)(xp + (size_t)r * DIN + q * 4));
            uint2 hi, lo; split2(v, hi, lo);
            char* p = smem + r * PITCH_B + q * 8;
            *(uint2*)(p + 0 * SPLIT_SZ) = hi;
            *(uint2*)(p + 1 * SPLIT_SZ) = lo;
        }
        CP_WAIT0();
    }
    __syncthreads();

    float acc0[NG * 4], acc1[NG * 4];
    #pragma unroll
    for (int i = 0; i < NG * 4; i++) { acc0[i] = 0.f; acc1[i] = 0.f; }

    const uint32_t a_loff = (uint32_t)((warp * 16 + (lane & 15)) * PITCH_B +
                                       ((lane >> 4) * 8) * 2);
    const uint32_t b_loff = (uint32_t)(((lane >> 4) * 8 + (lane & 7)) * PITCH_B +
                                       (((lane >> 3) & 1) * 8) * 2);

    for (int c = 0; c < NCHUNK; c++) {
        const int buf = c & 1;
        const uint32_t abase = sm_base + buf * BUF_SZ;
        const uint32_t nbase = sm_base + (buf ^ 1) * BUF_SZ;

        // ---- issue cp.async for next B tile (into buf^1) ----
        if (c < NCHUNK - 1) {
            const char* wp = (const char*)g_w1h + (size_t)(c + 1) * 128;
            #pragma unroll
            for (int i = 0; i < 4; i++) {
                int idx = tid + i * 256;
                int r = idx >> 3, q = idx & 7;
                cp16(nbase + B_OFF + (uint32_t)(r * PITCH_B + q * 16),
                     wp + (size_t)r * (DIN * 2) + q * 16);
            }
        }
        CP_COMMIT();

        // ---- prefetch x LDGs for chunk c+1 ----
        float4 xv[8];
        if (c < NCHUNK - 1) {
            const float* xp = x + (size_t)row0 * DIN + (c + 1) * KC;
            #pragma unroll
            for (int i = 0; i < 8; i++) {
                int idx = tid + i * 256;
                int r = idx >> 4, q = idx & 15;
                xv[i] = __ldg((const float4*)(xp + (size_t)r * DIN + q * 4));
            }
        }

        // ---- compute chunk c ----
        float* acc = buf ? acc1 : acc0;
        #pragma unroll
        for (int ks = 0; ks < 4; ks++) {
            uint32_t bf[NG * 2];
            #pragma unroll
            for (int gp = 0; gp < 6; gp++) {
                uint32_t addr = abase + B_OFF + gp * (16 * PITCH_B) +
                                b_loff + ks * 32;
                ldsm4(bf + 4 * gp, addr);
            }
            {
                uint32_t addr = abase + B_OFF + (96 + (lane & 7)) * PITCH_B +
                                (((lane >> 3) & 1) * 8) * 2 + ks * 32;
                ldsm2(bf + 24, addr);
            }
            #pragma unroll
            for (int s = 0; s < 2; s++) {
                uint32_t a[4];
                ldsm4(a, abase + s * SPLIT_SZ + a_loff + ks * 32);
                #pragma unroll
                for (int g = 0; g < NG; g++)
                    mma16816(acc + g * 4, a, bf + 2 * g);
            }
        }

        // ---- convert + STS chunk c+1 into buf^1 (no barrier needed:
        //      buf^1 readers finished before the previous iteration's sync) ----
        if (c < NCHUNK - 1) {
            char* base = smem + (buf ^ 1) * BUF_SZ;
            #pragma unroll
            for (int i = 0; i < 8; i++) {
                int idx = tid + i * 256;
                int r = idx >> 4, q = idx & 15;
                uint2 hi, lo; split2(xv[i], hi, lo);
                char* p = base + r * PITCH_B + q * 8;
                *(uint2*)(p + 0 * SPLIT_SZ) = hi;
                *(uint2*)(p + 1 * SPLIT_SZ) = lo;
            }
        }
        CP_WAIT0();
        __syncthreads();
    }

    // ---- epilogue: store h = acc0 + acc1 + b1 (cols < 100) ----
    const int gr = row0 + warp * 16 + (lane >> 2);
    const int cb = (lane & 3) * 2;
    #pragma unroll
    for (int g = 0; g < NG; g++) {
        int c0 = g * 8 + cb;
        if (c0 < H) {
            float2 lo, hi;
            lo.x = acc0[g*4+0] + acc1[g*4+0] + sb1[c0];
            lo.y = acc0[g*4+1] + acc1[g*4+1] + sb1[c0 + 1];
            hi.x = acc0[g*4+2] + acc1[g*4+2] + sb1[c0];
            hi.y = acc0[g*4+3] + acc1[g*4+3] + sb1[c0 + 1];
            *(float2*)(g_h + (size_t)gr * H + c0)       = lo;
            *(float2*)(g_h + (size_t)(gr + 8) * H + c0) = hi;
        }
    }

    // ---- fused BN pass 1: per-CTA partial sums over its 128 rows ----
    __threadfence_block();
    __syncthreads();
    float s = 0.f, s2 = 0.f;
    if (tid < 200) {
        int f = tid % 100;
        for (int rr = tid / 100; rr < 128; rr += 2) {
            float v = g_h[(size_t)(row0 + rr) * H + f];
            s += v;
            s2 = fmaf(v, v, s2);
        }
    }
    float* red = (float*)smem;
    if (tid < 200) { red[tid] = s; red[256 + tid] = s2; }
    __syncthreads();
    if (tid < 100) {
        g_part[blockIdx.x * 200 + tid]       = red[tid] + red[tid + 100];
        g_part[blockIdx.x * 200 + 100 + tid] = red[256 + tid] + red[356 + tid];
    }
}

// ============================================================
// Kernel S: finish batch-norm (one warp per feature)
// ============================================================
__global__ void bn_finish(const float* __restrict__ gamma,
                          const float* __restrict__ beta) {
    int f = blockIdx.x;
    int lane = threadIdx.x;
    float s = 0.f, s2 = 0.f;
    for (int c = lane; c < 256; c += 32) {
        s  += g_part[c * 200 + f];
        s2 += g_part[c * 200 + 100 + f];
    }
    #pragma unroll
    for (int off = 16; off > 0; off >>= 1) {
        s  += __shfl_xor_sync(0xffffffffu, s,  off);
        s2 += __shfl_xor_sync(0xffffffffu, s2, off);
    }
    if (lane == 0) {
        float mu  = s  * (1.f / B);
        float m2  = s2 * (1.f / B);
        float var = m2 - mu * mu;
        float sc  = gamma[f] * rsqrtf(var + BN_EPS);
        g_scale[f] = sc;
        g_shift[f] = fmaf(-mu, sc, beta[f]);
    }
}

// ============================================================
// Kernel H: head — one row/warp, popc GEMM2 + log_softmax
// ============================================================
__global__ __launch_bounds__(256)
void head(const float* __restrict__ b2, float* __restrict__ out) {
    __shared__ unsigned sw[DOUT * 4];
    __shared__ float    sb[DOUT];
    __shared__ float    ssc[H], ssh[H];

    const int tid = threadIdx.x;
    for (int i = tid; i < DOUT * 4; i += 256) sw[i] = g_w2p[i];
    for (int i = tid; i < DOUT;     i += 256) sb[i] = b2[i];
    if (tid < H) { ssc[tid] = g_scale[tid]; ssh[tid] = g_shift[tid]; }
    __syncthreads();

    const int lane = tid & 31;
    const int warp = tid >> 5;
    const int row  = blockIdx.x * 8 + warp;

    const float* hr = g_h + (size_t)row * H;
    bool p0 = fmaf(hr[lane],      ssc[lane],      ssh[lane])      >= 0.f;
    bool p1 = fmaf(hr[32 + lane], ssc[32 + lane], ssh[32 + lane]) >= 0.f;
    bool p2 = fmaf(hr[64 + lane], ssc[64 + lane], ssh[64 + lane]) >= 0.f;
    bool p3 = (lane < 4) ?
              (fmaf(hr[96 + lane], ssc[96 + lane], ssh[96 + lane]) >= 0.f) : false;
    unsigned a0 = __ballot_sync(0xffffffffu, p0);
    unsigned a1 = __ballot_sync(0xffffffffu, p1);
    unsigned a2 = __ballot_sync(0xffffffffu, p2);
    unsigned a3 = __ballot_sync(0xffffffffu, p3);

    float o[32];
    float mx = -1e30f;
    #pragma unroll
    for (int i = 0; i < 32; i++) {
        int j = i * 32 + lane;
        if (j < DOUT) {
            uint4 w = *(const uint4*)&sw[j * 4];
            int p = __popc(a0 ^ w.x) + __popc(a1 ^ w.y) +
                    __popc(a2 ^ w.z) + __popc(a3 ^ w.w);
            o[i] = (float)(H - 2 * p) + sb[j];
            mx = fmaxf(mx, o[i]);
        } else {
            o[i] = -1e30f;
        }
    }
    #pragma unroll
    for (int off = 16; off > 0; off >>= 1)
        mx = fmaxf(mx, __shfl_xor_sync(0xffffffffu, mx, off));

    float s = 0.f;
    #pragma unroll
    for (int i = 0; i < 32; i++)
        s += exp2f((o[i] - mx) * 1.4426950408889634f);
    #pragma unroll
    for (int off = 16; off > 0; off >>= 1)
        s += __shfl_xor_sync(0xffffffffu, s, off);

    float lse = fmaf(0.69314718055994531f, __log2f(s), mx);

    float* orow = out + (size_t)row * DOUT;
    #pragma unroll
    for (int i = 0; i < 32; i++) {
        int j = i * 32 + lane;
        if (j < DOUT) orow[j] = o[i] - lse;
    }
}

// ============================================================
// Launch
// ============================================================
extern "C" void kernel_launch(void* const* d_in, const int* in_sizes, int n_in,
                              void* d_out, int out_size) {
    (void)in_sizes; (void)n_in; (void)out_size;
    const float* x     = (const float*)d_in[0];
    const float* W1    = (const float*)d_in[1];
    const float* b1    = (const float*)d_in[2];
    const float* gamma = (const float*)d_in[3];
    const float* beta  = (const float*)d_in[4];
    const float* W2    = (const float*)d_in[5];
    const float* b2    = (const float*)d_in[6];
    float* out = (float*)d_out;

    static int smem_set = 0;
    if (!smem_set) {
        cudaFuncSetAttribute(gemm1_mma, cudaFuncAttributeMaxDynamicSharedMemorySize,
                             SMEM_TOTAL);
        smem_set = 1;
    }

    pack_all<<<2052, 256>>>(W1, W2);
    gemm1_mma<<<B / 128, 256, SMEM_TOTAL>>>(x, b1);
    bn_finish<<<H, 32>>>(gamma, beta);
    head<<<B / 8, 256>>>(b2, out);
}

// round 9
// speedup vs baseline: 2.5075x; 1.0844x over previous
#include <cuda_runtime.h>
#include <cuda_fp16.h>
#include <cstdint>

#define B    32768
#define DIN  4096
#define H    100
#define DOUT 1000
#define BN_EPS 1e-4f

#define KC      64
#define NCHUNK  (DIN / KC)         // 64
#define NPAD    128
#define NG      13                 // n8 groups (N=104)

#define PITCH_B   144
#define SPLIT_SZ  (128 * PITCH_B)  // 18432
#define BUF_SZ    (2 * SPLIT_SZ)   // A-hi + B = 36864
#define B_OFF     SPLIT_SZ
#define SB1_OFF   (2 * BUF_SZ)     // 73728
#define XRED_OFF  (SB1_OFF + 512)  // 74240, two 4KB buffers
#define SMEM_TOTAL (XRED_OFF + 8192)

// ---- scratch ----
__device__ float     g_h[(size_t)B * H];
__device__ float     g_scale[H];
__device__ float     g_shift[H];
__device__ float     g_bnd[H];
__device__ unsigned  g_w2p[DOUT * 4];
__device__ __half    g_w1h[(size_t)NPAD * DIN];
__device__ float     g_part[256 * 200];
__device__ float     g_xcs[256 * DIN];     // per-CTA x column-sum partials
__device__ float     g_xcolsum[DIN];

// ============================================================
// helpers
// ============================================================
__device__ __forceinline__ uint32_t smem_u32(const void* p) {
    uint32_t a;
    asm("{ .reg .u64 t; cvta.to.shared.u64 t, %1; cvt.u32.u64 %0, t; }"
        : "=r"(a) : "l"(p));
    return a;
}
__device__ __forceinline__ void ldsm4(uint32_t* r, uint32_t addr) {
    asm volatile("ldmatrix.sync.aligned.m8n8.x4.shared.b16 {%0,%1,%2,%3}, [%4];"
                 : "=r"(r[0]), "=r"(r[1]), "=r"(r[2]), "=r"(r[3]) : "r"(addr));
}
__device__ __forceinline__ void ldsm2(uint32_t* r, uint32_t addr) {
    asm volatile("ldmatrix.sync.aligned.m8n8.x2.shared.b16 {%0,%1}, [%2];"
                 : "=r"(r[0]), "=r"(r[1]) : "r"(addr));
}
__device__ __forceinline__ void mma16816(float* d, const uint32_t* a,
                                         const uint32_t* b) {
    asm volatile(
        "mma.sync.aligned.m16n8k16.row.col.f32.f16.f16.f32 "
        "{%0,%1,%2,%3}, {%4,%5,%6,%7}, {%8,%9}, {%0,%1,%2,%3};"
        : "+f"(d[0]), "+f"(d[1]), "+f"(d[2]), "+f"(d[3])
        : "r"(a[0]), "r"(a[1]), "r"(a[2]), "r"(a[3]), "r"(b[0]), "r"(b[1]));
}
__device__ __forceinline__ void cp16(uint32_t saddr, const void* g) {
    asm volatile("cp.async.cg.shared.global [%0], [%1], 16;"
                 :: "r"(saddr), "l"(g) : "memory");
}
#define CP_COMMIT() asm volatile("cp.async.commit_group;" ::: "memory")
#define CP_WAIT0()  asm volatile("cp.async.wait_group 0;"  ::: "memory")

// hi fp16 pack; lo residual returned for colsum
__device__ __forceinline__ uint2 hipack(float4 v, float4& lo) {
    __half2 a = __floats2half2_rn(v.x, v.y);
    __half2 b = __floats2half2_rn(v.z, v.w);
    float2 fa = __half22float2(a), fb = __half22float2(b);
    lo.x = v.x - fa.x; lo.y = v.y - fa.y;
    lo.z = v.z - fb.x; lo.w = v.w - fb.y;
    return make_uint2(*(uint32_t*)&a, *(uint32_t*)&b);
}

// ============================================================
// Kernel P: pack sign(W1)->fp16 and sign(W2)->bitmask
// ============================================================
__global__ void pack_all(const float* __restrict__ W1,
                         const float* __restrict__ W2) {
    int gb = blockIdx.x, tid = threadIdx.x;
    if (gb < 2048) {
        int idx = gb * 256 + tid;
        int row = idx >> 12, col = idx & 4095;
        float v = 0.f;
        if (row < H) v = (W1[(size_t)row * DIN + col] >= 0.f) ? 1.f : -1.f;
        g_w1h[(size_t)row * DIN + col] = __float2half(v);
    } else {
        int j = (gb - 2048) * 256 + tid;
        if (j >= DOUT) return;
        unsigned w0 = 0, w1 = 0, w2 = 0, w3 = 0;
        const float* r = W2 + (size_t)j * H;
        #pragma unroll 4
        for (int k = 0; k < 32; k++)  if (r[k]      >= 0.f) w0 |= (1u << k);
        #pragma unroll 4
        for (int k = 0; k < 32; k++)  if (r[32 + k] >= 0.f) w1 |= (1u << k);
        #pragma unroll 4
        for (int k = 0; k < 32; k++)  if (r[64 + k] >= 0.f) w2 |= (1u << k);
        #pragma unroll
        for (int k = 0; k < 4;  k++)  if (r[96 + k] >= 0.f) w3 |= (1u << k);
        g_w2p[j * 4 + 0] = w0; g_w2p[j * 4 + 1] = w1;
        g_w2p[j * 4 + 2] = w2; g_w2p[j * 4 + 3] = w3;
    }
}

// ============================================================
// Kernel G: gemm1 hi-only fp16 MMA + fused x-colsums + BN partials
// ============================================================
__global__ void __launch_bounds__(256, 1)
gemm1_mma(const float* __restrict__ x, const float* __restrict__ b1) {
    extern __shared__ char smem[];
    const uint32_t sm_base = smem_u32(smem);
    const int tid  = threadIdx.x;
    const int warp = tid >> 5;
    const int lane = tid & 31;
    const int row0 = blockIdx.x * 128;

    float* sb1 = (float*)(smem + SB1_OFF);
    if (tid < 104) sb1[tid] = (tid < H) ? b1[tid] : 0.f;

    // ---- prologue: stage chunk 0 (buf 0) + fold cs(0) -> xred[0] ----
    {
        #pragma unroll
        for (int i = 0; i < 4; i++) {
            int idx = tid + i * 256;
            int r = idx >> 3, q = idx & 7;
            cp16(sm_base + B_OFF + (uint32_t)(r * PITCH_B + q * 16),
                 (const char*)g_w1h + (size_t)r * (DIN * 2) + q * 16);
        }
        CP_COMMIT();
        const float* xp = x + (size_t)row0 * DIN;
        float cs0 = 0.f, cs1 = 0.f, cs2 = 0.f, cs3 = 0.f;
        #pragma unroll
        for (int i = 0; i < 8; i++) {
            int idx = tid + i * 256;
            int r = idx >> 4, q = idx & 15;
            float4 v = __ldg((const float4*)(xp + (size_t)r * DIN + q * 4));
            float4 lo;
            uint2 hi = hipack(v, lo);
            *(uint2*)(smem + r * PITCH_B + q * 8) = hi;
            cs0 += lo.x; cs1 += lo.y; cs2 += lo.z; cs3 += lo.w;
        }
        float* xw = (float*)(smem + XRED_OFF);
        *(float4*)&xw[tid * 4] = make_float4(cs0, cs1, cs2, cs3);
        CP_WAIT0();
    }
    __syncthreads();

    float acc[NG * 4];
    #pragma unroll
    for (int i = 0; i < NG * 4; i++) acc[i] = 0.f;

    const uint32_t a_loff = (uint32_t)((warp * 16 + (lane & 15)) * PITCH_B +
                                       ((lane >> 4) * 8) * 2);
    const uint32_t b_loff = (uint32_t)(((lane >> 4) * 8 + (lane & 7)) * PITCH_B +
                                       (((lane >> 3) & 1) * 8) * 2);

    for (int c = 0; c < NCHUNK; c++) {
        const int buf = c & 1;
        const uint32_t abase = sm_base + buf * BUF_SZ;
        const uint32_t nbase = sm_base + (buf ^ 1) * BUF_SZ;

        // ---- reduce xred (chunk c lo colsums) -> g_xcs ----
        if (tid < 64) {
            const float* xr = (const float*)(smem + XRED_OFF + (c & 1) * 4096);
            int q = tid >> 2, j = tid & 3;
            float sum = 0.f;
            #pragma unroll
            for (int m = 0; m < 16; m++) sum += xr[(q + 16 * m) * 4 + j];
            g_xcs[blockIdx.x * DIN + c * 64 + tid] = sum;
        }

        // ---- cp.async next B tile into buf^1 ----
        if (c < NCHUNK - 1) {
            const char* wp = (const char*)g_w1h + (size_t)(c + 1) * 128;
            #pragma unroll
            for (int i = 0; i < 4; i++) {
                int idx = tid + i * 256;
                int r = idx >> 3, q = idx & 7;
                cp16(nbase + B_OFF + (uint32_t)(r * PITCH_B + q * 16),
                     wp + (size_t)r * (DIN * 2) + q * 16);
            }
        }
        CP_COMMIT();

        // ---- prefetch x(c+1) ----
        float4 xv[8];
        if (c < NCHUNK - 1) {
            const float* xp = x + (size_t)row0 * DIN + (c + 1) * KC;
            #pragma unroll
            for (int i = 0; i < 8; i++) {
                int idx = tid + i * 256;
                int r = idx >> 4, q = idx & 15;
                xv[i] = __ldg((const float4*)(xp + (size_t)r * DIN + q * 4));
            }
        }

        // ---- compute chunk c ----
        #pragma unroll
        for (int ks = 0; ks < 4; ks++) {
            uint32_t bf[NG * 2];
            #pragma unroll
            for (int gp = 0; gp < 6; gp++)
                ldsm4(bf + 4 * gp, abase + B_OFF + gp * (16 * PITCH_B) +
                      b_loff + ks * 32);
            ldsm2(bf + 24, abase + B_OFF + (96 + (lane & 7)) * PITCH_B +
                  (((lane >> 3) & 1) * 8) * 2 + ks * 32);
            uint32_t a[4];
            ldsm4(a, abase + a_loff + ks * 32);
            #pragma unroll
            for (int g = 0; g < NG; g++)
                mma16816(acc + g * 4, a, bf + 2 * g);
        }

        // ---- convert + STS x(c+1) + fold cs(c+1) -> xred[(c+1)&1] ----
        if (c < NCHUNK - 1) {
            char* base = smem + (buf ^ 1) * BUF_SZ;
            float cs0 = 0.f, cs1 = 0.f, cs2 = 0.f, cs3 = 0.f;
            #pragma unroll
            for (int i = 0; i < 8; i++) {
                int idx = tid + i * 256;
                int r = idx >> 4, q = idx & 15;
                float4 lo;
                uint2 hi = hipack(xv[i], lo);
                *(uint2*)(base + r * PITCH_B + q * 8) = hi;
                cs0 += lo.x; cs1 += lo.y; cs2 += lo.z; cs3 += lo.w;
            }
            float* xw = (float*)(smem + XRED_OFF + ((c + 1) & 1) * 4096);
            *(float4*)&xw[tid * 4] = make_float4(cs0, cs1, cs2, cs3);
        }
        CP_WAIT0();
        __syncthreads();
    }

    // ---- epilogue: h_hi + b1 ----
    const int gr = row0 + warp * 16 + (lane >> 2);
    const int cb = (lane & 3) * 2;
    #pragma unroll
    for (int g = 0; g < NG; g++) {
        int c0 = g * 8 + cb;
        if (c0 < H) {
            float2 lo, hi;
            lo.x = acc[g*4+0] + sb1[c0];
            lo.y = acc[g*4+1] + sb1[c0 + 1];
            hi.x = acc[g*4+2] + sb1[c0];
            hi.y = acc[g*4+3] + sb1[c0 + 1];
            *(float2*)(g_h + (size_t)gr * H + c0)       = lo;
            *(float2*)(g_h + (size_t)(gr + 8) * H + c0) = hi;
        }
    }

    // ---- fused BN pass 1 (sum, sum-of-squares of h_hi) ----
    __threadfence_block();
    __syncthreads();
    float s = 0.f, s2 = 0.f;
    if (tid < 200) {
        int f = tid % 100;
        for (int rr = tid / 100; rr < 128; rr += 2) {
            float v = g_h[(size_t)(row0 + rr) * H + f];
            s += v;
            s2 = fmaf(v, v, s2);
        }
    }
    float* red = (float*)smem;
    if (tid < 200) { red[tid] = s; red[256 + tid] = s2; }
    __syncthreads();
    if (tid < 100) {
        g_part[blockIdx.x * 200 + tid]       = red[tid] + red[tid + 100];
        g_part[blockIdx.x * 200 + 100 + tid] = red[256 + tid] + red[356 + tid];
    }
}

// ============================================================
// Kernel R: reduce per-CTA lo colsums -> g_xcolsum
// ============================================================
__global__ void xcs_reduce() {
    int k = blockIdx.x * 256 + threadIdx.x;   // < 4096
    float s = 0.f;
    for (int c = 0; c < 256; c++) s += g_xcs[c * DIN + k];
    g_xcolsum[k] = s;
}

// ============================================================
// Kernel S: bn_finish — exact mu via colsum dot (note: colsum holds
// lo = x - fp16(x); exact mu uses mean(h_hi) + lo-correction)
// ============================================================
__global__ void bn_finish(const float* __restrict__ gamma,
                          const float* __restrict__ beta,
                          const float* __restrict__ b1) {
    int f = blockIdx.x;
    int lane = threadIdx.x;

    // sums of h_hi (and squares) from per-CTA partials
    float s = 0.f, s2 = 0.f;
    for (int c = lane; c < 256; c += 32) {
        s  += g_part[c * 200 + f];
        s2 += g_part[c * 200 + 100 + f];
    }
    // lo-correction dot: sum_k colsum_lo[k] * w[f][k]   (Kahan)
    float d = 0.f, comp = 0.f;
    const __half* wr = g_w1h + (size_t)f * DIN;
    #pragma unroll 4
    for (int t = 0; t < 128; t++) {
        int k = lane + 32 * t;
        float term = g_xcolsum[k] * __half2float(wr[k]);
        float y  = __fsub_rn(term, comp);
        float t2 = __fadd_rn(d, y);
        comp = __fsub_rn(__fsub_rn(t2, d), y);
        d = t2;
    }
    d = __fadd_rn(d, comp);
    #pragma unroll
    for (int off = 16; off > 0; off >>= 1) {
        s  += __shfl_xor_sync(0xffffffffu, s,  off);
        s2 += __shfl_xor_sync(0xffffffffu, s2, off);
        d  += __shfl_xor_sync(0xffffffffu, d,  off);
    }
    if (lane == 0) {
        float mu_hi = s * (1.f / B);
        float mu    = mu_hi + d * (1.f / B);     // exact mean of h
        float m2    = s2 * (1.f / B);
        float var   = m2 - mu_hi * mu_hi;        // var from h_hi (negligible diff)
        float sc    = gamma[f] * rsqrtf(var + BN_EPS);
        g_scale[f] = sc;
        g_shift[f] = fmaf(-mu, sc, beta[f]);
        g_bnd[f]   = mu - beta[f] / sc;          // sign boundary in h units
    }
}

// ============================================================
// Kernel F: fixup — recompute exactly all h within 0.12 of boundary
// ============================================================
__global__ __launch_bounds__(256)
void fixup(const float* __restrict__ x, const float* __restrict__ b1) {
    __shared__ float sbnd[H], sb1s[H];
    const int tid = threadIdx.x;
    if (tid < H) { sbnd[tid] = g_bnd[tid]; sb1s[tid] = b1[tid]; }
    __syncthreads();

    const int lane = tid & 31;
    const int warp = tid >> 5;
    const int row  = blockIdx.x * 8 + warp;
    float* hr = g_h + (size_t)row * H;
    const float* xr = x + (size_t)row * DIN;

    #pragma unroll
    for (int grp = 0; grp < 4; grp++) {
        int f = grp * 32 + lane;
        bool flag = false;
        if (f < H) flag = fabsf(hr[f] - sbnd[f]) < 0.12f;
        unsigned m = __ballot_sync(0xffffffffu, flag);
        while (m) {
            int b = __ffs(m) - 1;
            m &= m - 1;
            int feat = grp * 32 + b;
            const __half* wr = g_w1h + (size_t)feat * DIN;
            float s = 0.f, comp = 0.f;
            #pragma unroll 4
            for (int t = 0; t < 128; t++) {
                int k = lane + 32 * t;
                float term = xr[k] * __half2float(wr[k]);  // exact: w = +/-1
                float y  = __fsub_rn(term, comp);
                float t2 = __fadd_rn(s, y);
                comp = __fsub_rn(__fsub_rn(t2, s), y);
                s = t2;
            }
            s = __fadd_rn(s, comp);
            #pragma unroll
            for (int off = 16; off > 0; off >>= 1)
                s += __shfl_xor_sync(0xffffffffu, s, off);
            if (lane == 0) hr[feat] = s + sb1s[feat];
        }
    }
}

// ============================================================
// Kernel H: head — one row/warp, popc GEMM2 + log_softmax
// ============================================================
__global__ __launch_bounds__(256)
void head(const float* __restrict__ b2, float* __restrict__ out) {
    __shared__ unsigned sw[DOUT * 4];
    __shared__ float    sb[DOUT];
    __shared__ float    ssc[H], ssh[H];

    const int tid = threadIdx.x;
    for (int i = tid; i < DOUT * 4; i += 256) sw[i] = g_w2p[i];
    for (int i = tid; i < DOUT;     i += 256) sb[i] = b2[i];
    if (tid < H) { ssc[tid] = g_scale[tid]; ssh[tid] = g_shift[tid]; }
    __syncthreads();

    const int lane = tid & 31;
    const int warp = tid >> 5;
    const int row  = blockIdx.x * 8 + warp;

    const float* hr = g_h + (size_t)row * H;
    bool p0 = fmaf(hr[lane],      ssc[lane],      ssh[lane])      >= 0.f;
    bool p1 = fmaf(hr[32 + lane], ssc[32 + lane], ssh[32 + lane]) >= 0.f;
    bool p2 = fmaf(hr[64 + lane], ssc[64 + lane], ssh[64 + lane]) >= 0.f;
    bool p3 = (lane < 4) ?
              (fmaf(hr[96 + lane], ssc[96 + lane], ssh[96 + lane]) >= 0.f) : false;
    unsigned a0 = __ballot_sync(0xffffffffu, p0);
    unsigned a1 = __ballot_sync(0xffffffffu, p1);
    unsigned a2 = __ballot_sync(0xffffffffu, p2);
    unsigned a3 = __ballot_sync(0xffffffffu, p3);

    float o[32];
    float mx = -1e30f;
    #pragma unroll
    for (int i = 0; i < 32; i++) {
        int j = i * 32 + lane;
        if (j < DOUT) {
            uint4 w = *(const uint4*)&sw[j * 4];
            int p = __popc(a0 ^ w.x) + __popc(a1 ^ w.y) +
                    __popc(a2 ^ w.z) + __popc(a3 ^ w.w);
            o[i] = (float)(H - 2 * p) + sb[j];
            mx = fmaxf(mx, o[i]);
        } else {
            o[i] = -1e30f;
        }
    }
    #pragma unroll
    for (int off = 16; off > 0; off >>= 1)
        mx = fmaxf(mx, __shfl_xor_sync(0xffffffffu, mx, off));

    float s = 0.f;
    #pragma unroll
    for (int i = 0; i < 32; i++)
        s += exp2f((o[i] - mx) * 1.4426950408889634f);
    #pragma unroll
    for (int off = 16; off > 0; off >>= 1)
        s += __shfl_xor_sync(0xffffffffu, s, off);

    float lse = fmaf(0.69314718055994531f, __log2f(s), mx);

    float* orow = out + (size_t)row * DOUT;
    #pragma unroll
    for (int i = 0; i < 32; i++) {
        int j = i * 32 + lane;
        if (j < DOUT) orow[j] = o[i] - lse;
    }
}

// ============================================================
// Launch
// ============================================================
extern "C" void kernel_launch(void* const* d_in, const int* in_sizes, int n_in,
                              void* d_out, int out_size) {
    (void)in_sizes; (void)n_in; (void)out_size;
    const float* x     = (const float*)d_in[0];
    const float* W1    = (const float*)d_in[1];
    const float* b1    = (const float*)d_in[2];
    const float* gamma = (const float*)d_in[3];
    const float* beta  = (const float*)d_in[4];
    const float* W2    = (const float*)d_in[5];
    const float* b2    = (const float*)d_in[6];
    float* out = (float*)d_out;

    static int smem_set = 0;
    if (!smem_set) {
        cudaFuncSetAttribute(gemm1_mma, cudaFuncAttributeMaxDynamicSharedMemorySize,
                             SMEM_TOTAL);
        smem_set = 1;
    }

    pack_all<<<2052, 256>>>(W1, W2);
    gemm1_mma<<<B / 128, 256, SMEM_TOTAL>>>(x, b1);
    xcs_reduce<<<DIN / 256, 256>>>();
    bn_finish<<<H, 32>>>(gamma, beta, b1);
    fixup<<<B / 8, 256>>>(x, b1);
    head<<<B / 8, 256>>>(b2, out);
}

// round 10
// speedup vs baseline: 2.6394x; 1.0526x over previous
#include <cuda_runtime.h>
#include <cuda_fp16.h>
#include <cstdint>

#define B    32768
#define DIN  4096
#define H    100
#define DOUT 1000
#define BN_EPS 1e-4f

#define KC      64
#define NCHUNK  (DIN / KC)         // 64
#define NPAD    128
#define NG      13                 // n8 groups (N=104)

#define PITCH_B   144
#define SPLIT_SZ  (128 * PITCH_B)  // 18432
#define BUF_SZ    (2 * SPLIT_SZ)   // A-hi + B = 36864
#define B_OFF     SPLIT_SZ
#define SB1_OFF   (2 * BUF_SZ)     // 73728
#define XRED_OFF  (SB1_OFF + 512)  // 74240, two 4KB buffers
#define SMEM_TOTAL (XRED_OFF + 8192)

// ---- scratch ----
__device__ float     g_h[(size_t)B * H];
__device__ float     g_scale[H];
__device__ float     g_shift[H];
__device__ unsigned  g_w2p[DOUT * 4];
__device__ __half    g_w1h[(size_t)NPAD * DIN];
__device__ float     g_part[256 * 200];
__device__ float     g_xcs[256 * DIN];
__device__ float     g_xcolsum[DIN];

// ============================================================
// helpers
// ============================================================
__device__ __forceinline__ uint32_t smem_u32(const void* p) {
    uint32_t a;
    asm("{ .reg .u64 t; cvta.to.shared.u64 t, %1; cvt.u32.u64 %0, t; }"
        : "=r"(a) : "l"(p));
    return a;
}
__device__ __forceinline__ void ldsm4(uint32_t* r, uint32_t addr) {
    asm volatile("ldmatrix.sync.aligned.m8n8.x4.shared.b16 {%0,%1,%2,%3}, [%4];"
                 : "=r"(r[0]), "=r"(r[1]), "=r"(r[2]), "=r"(r[3]) : "r"(addr));
}
__device__ __forceinline__ void ldsm2(uint32_t* r, uint32_t addr) {
    asm volatile("ldmatrix.sync.aligned.m8n8.x2.shared.b16 {%0,%1}, [%2];"
                 : "=r"(r[0]), "=r"(r[1]) : "r"(addr));
}
__device__ __forceinline__ void mma16816(float* d, const uint32_t* a,
                                         const uint32_t* b) {
    asm volatile(
        "mma.sync.aligned.m16n8k16.row.col.f32.f16.f16.f32 "
        "{%0,%1,%2,%3}, {%4,%5,%6,%7}, {%8,%9}, {%0,%1,%2,%3};"
        : "+f"(d[0]), "+f"(d[1]), "+f"(d[2]), "+f"(d[3])
        : "r"(a[0]), "r"(a[1]), "r"(a[2]), "r"(a[3]), "r"(b[0]), "r"(b[1]));
}
__device__ __forceinline__ void cp16(uint32_t saddr, const void* g) {
    asm volatile("cp.async.cg.shared.global [%0], [%1], 16;"
                 :: "r"(saddr), "l"(g) : "memory");
}
#define CP_COMMIT() asm volatile("cp.async.commit_group;" ::: "memory")
#define CP_WAIT0()  asm volatile("cp.async.wait_group 0;"  ::: "memory")

__device__ __forceinline__ uint2 hipack(float4 v, float4& lo) {
    __half2 a = __floats2half2_rn(v.x, v.y);
    __half2 b = __floats2half2_rn(v.z, v.w);
    float2 fa = __half22float2(a), fb = __half22float2(b);
    lo.x = v.x - fa.x; lo.y = v.y - fa.y;
    lo.z = v.z - fb.x; lo.w = v.w - fb.y;
    return make_uint2(*(uint32_t*)&a, *(uint32_t*)&b);
}

// ============================================================
// Kernel P: pack sign(W1)->fp16 and sign(W2)->bitmask
// ============================================================
__global__ void pack_all(const float* __restrict__ W1,
                         const float* __restrict__ W2) {
    int gb = blockIdx.x, tid = threadIdx.x;
    if (gb < 2048) {
        int idx = gb * 256 + tid;
        int row = idx >> 12, col = idx & 4095;
        float v = 0.f;
        if (row < H) v = (W1[(size_t)row * DIN + col] >= 0.f) ? 1.f : -1.f;
        g_w1h[(size_t)row * DIN + col] = __float2half(v);
    } else {
        int j = (gb - 2048) * 256 + tid;
        if (j >= DOUT) return;
        unsigned w0 = 0, w1 = 0, w2 = 0, w3 = 0;
        const float* r = W2 + (size_t)j * H;
        #pragma unroll 4
        for (int k = 0; k < 32; k++)  if (r[k]      >= 0.f) w0 |= (1u << k);
        #pragma unroll 4
        for (int k = 0; k < 32; k++)  if (r[32 + k] >= 0.f) w1 |= (1u << k);
        #pragma unroll 4
        for (int k = 0; k < 32; k++)  if (r[64 + k] >= 0.f) w2 |= (1u << k);
        #pragma unroll
        for (int k = 0; k < 4;  k++)  if (r[96 + k] >= 0.f) w3 |= (1u << k);
        g_w2p[j * 4 + 0] = w0; g_w2p[j * 4 + 1] = w1;
        g_w2p[j * 4 + 2] = w2; g_w2p[j * 4 + 3] = w3;
    }
}

// ============================================================
// Kernel G: gemm1 hi-only fp16 MMA + fused x-colsums + BN partials
// ============================================================
__global__ void __launch_bounds__(256, 1)
gemm1_mma(const float* __restrict__ x, const float* __restrict__ b1) {
    extern __shared__ char smem[];
    const uint32_t sm_base = smem_u32(smem);
    const int tid  = threadIdx.x;
    const int warp = tid >> 5;
    const int lane = tid & 31;
    const int row0 = blockIdx.x * 128;

    float* sb1 = (float*)(smem + SB1_OFF);
    if (tid < 104) sb1[tid] = (tid < H) ? b1[tid] : 0.f;

    {
        #pragma unroll
        for (int i = 0; i < 4; i++) {
            int idx = tid + i * 256;
            int r = idx >> 3, q = idx & 7;
            cp16(sm_base + B_OFF + (uint32_t)(r * PITCH_B + q * 16),
                 (const char*)g_w1h + (size_t)r * (DIN * 2) + q * 16);
        }
        CP_COMMIT();
        const float* xp = x + (size_t)row0 * DIN;
        float cs0 = 0.f, cs1 = 0.f, cs2 = 0.f, cs3 = 0.f;
        #pragma unroll
        for (int i = 0; i < 8; i++) {
            int idx = tid + i * 256;
            int r = idx >> 4, q = idx & 15;
            float4 v = __ldg((const float4*)(xp + (size_t)r * DIN + q * 4));
            float4 lo;
            uint2 hi = hipack(v, lo);
            *(uint2*)(smem + r * PITCH_B + q * 8) = hi;
            cs0 += lo.x; cs1 += lo.y; cs2 += lo.z; cs3 += lo.w;
        }
        float* xw = (float*)(smem + XRED_OFF);
        *(float4*)&xw[tid * 4] = make_float4(cs0, cs1, cs2, cs3);
        CP_WAIT0();
    }
    __syncthreads();

    float acc[NG * 4];
    #pragma unroll
    for (int i = 0; i < NG * 4; i++) acc[i] = 0.f;

    const uint32_t a_loff = (uint32_t)((warp * 16 + (lane & 15)) * PITCH_B +
                                       ((lane >> 4) * 8) * 2);
    const uint32_t b_loff = (uint32_t)(((lane >> 4) * 8 + (lane & 7)) * PITCH_B +
                                       (((lane >> 3) & 1) * 8) * 2);

    for (int c = 0; c < NCHUNK; c++) {
        const int buf = c & 1;
        const uint32_t abase = sm_base + buf * BUF_SZ;
        const uint32_t nbase = sm_base + (buf ^ 1) * BUF_SZ;

        if (tid < 64) {
            const float* xr = (const float*)(smem + XRED_OFF + (c & 1) * 4096);
            int q = tid >> 2, j = tid & 3;
            float sum = 0.f;
            #pragma unroll
            for (int m = 0; m < 16; m++) sum += xr[(q + 16 * m) * 4 + j];
            g_xcs[blockIdx.x * DIN + c * 64 + tid] = sum;
        }

        if (c < NCHUNK - 1) {
            const char* wp = (const char*)g_w1h + (size_t)(c + 1) * 128;
            #pragma unroll
            for (int i = 0; i < 4; i++) {
                int idx = tid + i * 256;
                int r = idx >> 3, q = idx & 7;
                cp16(nbase + B_OFF + (uint32_t)(r * PITCH_B + q * 16),
                     wp + (size_t)r * (DIN * 2) + q * 16);
            }
        }
        CP_COMMIT();

        float4 xv[8];
        if (c < NCHUNK - 1) {
            const float* xp = x + (size_t)row0 * DIN + (c + 1) * KC;
            #pragma unroll
            for (int i = 0; i < 8; i++) {
                int idx = tid + i * 256;
                int r = idx >> 4, q = idx & 15;
                xv[i] = __ldg((const float4*)(xp + (size_t)r * DIN + q * 4));
            }
        }

        #pragma unroll
        for (int ks = 0; ks < 4; ks++) {
            uint32_t bf[NG * 2];
            #pragma unroll
            for (int gp = 0; gp < 6; gp++)
                ldsm4(bf + 4 * gp, abase + B_OFF + gp * (16 * PITCH_B) +
                      b_loff + ks * 32);
            ldsm2(bf + 24, abase + B_OFF + (96 + (lane & 7)) * PITCH_B +
                  (((lane >> 3) & 1) * 8) * 2 + ks * 32);
            uint32_t a[4];
            ldsm4(a, abase + a_loff + ks * 32);
            #pragma unroll
            for (int g = 0; g < NG; g++)
                mma16816(acc + g * 4, a, bf + 2 * g);
        }

        if (c < NCHUNK - 1) {
            char* base = smem + (buf ^ 1) * BUF_SZ;
            float cs0 = 0.f, cs1 = 0.f, cs2 = 0.f, cs3 = 0.f;
            #pragma unroll
            for (int i = 0; i < 8; i++) {
                int idx = tid + i * 256;
                int r = idx >> 4, q = idx & 15;
                float4 lo;
                uint2 hi = hipack(xv[i], lo);
                *(uint2*)(base + r * PITCH_B + q * 8) = hi;
                cs0 += lo.x; cs1 += lo.y; cs2 += lo.z; cs3 += lo.w;
            }
            float* xw = (float*)(smem + XRED_OFF + ((c + 1) & 1) * 4096);
            *(float4*)&xw[tid * 4] = make_float4(cs0, cs1, cs2, cs3);
        }
        CP_WAIT0();
        __syncthreads();
    }

    const int gr = row0 + warp * 16 + (lane >> 2);
    const int cb = (lane & 3) * 2;
    #pragma unroll
    for (int g = 0; g < NG; g++) {
        int c0 = g * 8 + cb;
        if (c0 < H) {
            float2 lo, hi;
            lo.x = acc[g*4+0] + sb1[c0];
            lo.y = acc[g*4+1] + sb1[c0 + 1];
            hi.x = acc[g*4+2] + sb1[c0];
            hi.y = acc[g*4+3] + sb1[c0 + 1];
            *(float2*)(g_h + (size_t)gr * H + c0)       = lo;
            *(float2*)(g_h + (size_t)(gr + 8) * H + c0) = hi;
        }
    }

    __threadfence_block();
    __syncthreads();
    float s = 0.f, s2 = 0.f;
    if (tid < 200) {
        int f = tid % 100;
        for (int rr = tid / 100; rr < 128; rr += 2) {
            float v = g_h[(size_t)(row0 + rr) * H + f];
            s += v;
            s2 = fmaf(v, v, s2);
        }
    }
    float* red = (float*)smem;
    if (tid < 200) { red[tid] = s; red[256 + tid] = s2; }
    __syncthreads();
    if (tid < 100) {
        g_part[blockIdx.x * 200 + tid]       = red[tid] + red[tid + 100];
        g_part[blockIdx.x * 200 + 100 + tid] = red[256 + tid] + red[356 + tid];
    }
}

// ============================================================
// Kernel R: reduce per-CTA lo colsums -> g_xcolsum (4-way c-split)
// ============================================================
__global__ void xcs_reduce() {
    __shared__ float sm[256];
    int kk = threadIdx.x & 63, cg = threadIdx.x >> 6;
    int k = blockIdx.x * 64 + kk;
    float s = 0.f;
    for (int c = cg * 64; c < cg * 64 + 64; c++) s += g_xcs[c * DIN + k];
    sm[threadIdx.x] = s;
    __syncthreads();
    if (cg == 0)
        g_xcolsum[k] = sm[kk] + sm[64 + kk] + sm[128 + kk] + sm[192 + kk];
}

// ============================================================
// Kernel S: bn_finish — 256 threads/feature, exact mu
// ============================================================
__global__ void bn_finish(const float* __restrict__ gamma,
                          const float* __restrict__ beta) {
    __shared__ float rs[256], rs2[256], rd[256];
    const int f   = blockIdx.x;
    const int tid = threadIdx.x;

    float s  = g_part[tid * 200 + f];
    float s2 = g_part[tid * 200 + 100 + f];

    float d = 0.f;
    const __half* wr = g_w1h + (size_t)f * DIN;
    #pragma unroll
    for (int t = 0; t < 16; t++) {
        int k = tid + 256 * t;
        d = fmaf(g_xcolsum[k], __half2float(wr[k]), d);
    }
    rs[tid] = s; rs2[tid] = s2; rd[tid] = d;
    __syncthreads();
    #pragma unroll
    for (int off = 128; off > 0; off >>= 1) {
        if (tid < off) {
            rs[tid]  += rs[tid + off];
            rs2[tid] += rs2[tid + off];
            rd[tid]  += rd[tid + off];
        }
        __syncthreads();
    }
    if (tid == 0) {
        float mu_hi = rs[0] * (1.f / B);
        float mu    = mu_hi + rd[0] * (1.f / B);
        float m2    = rs2[0] * (1.f / B);
        float var   = m2 - mu_hi * mu_hi;
        float sc    = gamma[f] * rsqrtf(var + BN_EPS);
        g_scale[f] = sc;
        g_shift[f] = fmaf(-mu, sc, beta[f]);
    }
}

// ============================================================
// Kernel H: head — fixup fused before ballots
// ============================================================
__global__ __launch_bounds__(256)
void head(const float* __restrict__ x, const float* __restrict__ b1,
          const float* __restrict__ b2, float* __restrict__ out) {
    __shared__ unsigned sw[DOUT * 4];
    __shared__ float    sb[DOUT];
    __shared__ float    ssc[H], ssh[H], sb1s[H];

    const int tid = threadIdx.x;
    for (int i = tid; i < DOUT * 4; i += 256) sw[i] = g_w2p[i];
    for (int i = tid; i < DOUT;     i += 256) sb[i] = b2[i];
    if (tid < H) { ssc[tid] = g_scale[tid]; ssh[tid] = g_shift[tid];
                   sb1s[tid] = b1[tid]; }
    __syncthreads();

    const int lane = tid & 31;
    const int warp = tid >> 5;
    const int row  = blockIdx.x * 8 + warp;

    const float* hr = g_h + (size_t)row * H;
    const float* xr = x + (size_t)row * DIN;

    float hn0 = fmaf(hr[lane],      ssc[lane],      ssh[lane]);
    float hn1 = fmaf(hr[32 + lane], ssc[32 + lane], ssh[32 + lane]);
    float hn2 = fmaf(hr[64 + lane], ssc[64 + lane], ssh[64 + lane]);
    float hn3 = (lane < 4) ?
                fmaf(hr[96 + lane], ssc[96 + lane], ssh[96 + lane]) : -1.f;

    // ---- inline exact fixup of boundary entries ----
    #pragma unroll
    for (int grp = 0; grp < 4; grp++) {
        float hn = (grp == 0) ? hn0 : (grp == 1) ? hn1 : (grp == 2) ? hn2 : hn3;
        bool flag = (grp < 3 || lane < 4) &&
                    (fabsf(hn) < 0.12f * fabsf(ssc[(grp * 32 + lane) % H]));
        unsigned m = __ballot_sync(0xffffffffu, flag);
        while (m) {
            int bpos = __ffs(m) - 1;
            m &= m - 1;
            int feat = grp * 32 + bpos;
            const __half* wr = g_w1h + (size_t)feat * DIN;
            float s = 0.f, comp = 0.f;
            #pragma unroll 4
            for (int t = 0; t < 128; t++) {
                int k = lane + 32 * t;
                float term = xr[k] * __half2float(wr[k]);
                float y  = __fsub_rn(term, comp);
                float t2 = __fadd_rn(s, y);
                comp = __fsub_rn(__fsub_rn(t2, s), y);
                s = t2;
            }
            s = __fadd_rn(s, comp);
            #pragma unroll
            for (int off = 16; off > 0; off >>= 1)
                s += __shfl_xor_sync(0xffffffffu, s, off);
            if (lane == bpos) {
                float fix = fmaf(s + sb1s[feat], ssc[feat], ssh[feat]);
                if (grp == 0) hn0 = fix;
                else if (grp == 1) hn1 = fix;
                else if (grp == 2) hn2 = fix;
                else hn3 = fix;
            }
        }
    }

    unsigned a0 = __ballot_sync(0xffffffffu, hn0 >= 0.f);
    unsigned a1 = __ballot_sync(0xffffffffu, hn1 >= 0.f);
    unsigned a2 = __ballot_sync(0xffffffffu, hn2 >= 0.f);
    unsigned a3 = __ballot_sync(0xffffffffu, (lane < 4) && (hn3 >= 0.f));

    float o[32];
    float mx = -1e30f;
    #pragma unroll
    for (int i = 0; i < 32; i++) {
        int j = i * 32 + lane;
        if (j < DOUT) {
            uint4 w = *(const uint4*)&sw[j * 4];
            int p = __popc(a0 ^ w.x) + __popc(a1 ^ w.y) +
                    __popc(a2 ^ w.z) + __popc(a3 ^ w.w);
            o[i] = (float)(H - 2 * p) + sb[j];
            mx = fmaxf(mx, o[i]);
        } else {
            o[i] = -1e30f;
        }
    }
    #pragma unroll
    for (int off = 16; off > 0; off >>= 1)
        mx = fmaxf(mx, __shfl_xor_sync(0xffffffffu, mx, off));

    float s = 0.f;
    #pragma unroll
    for (int i = 0; i < 32; i++)
        s += exp2f((o[i] - mx) * 1.4426950408889634f);
    #pragma unroll
    for (int off = 16; off > 0; off >>= 1)
        s += __shfl_xor_sync(0xffffffffu, s, off);

    float lse = fmaf(0.69314718055994531f, __log2f(s), mx);

    float* orow = out + (size_t)row * DOUT;
    #pragma unroll
    for (int i = 0; i < 32; i++) {
        int j = i * 32 + lane;
        if (j < DOUT) orow[j] = o[i] - lse;
    }
}

// ============================================================
// Launch
// ============================================================
extern "C" void kernel_launch(void* const* d_in, const int* in_sizes, int n_in,
                              void* d_out, int out_size) {
    (void)in_sizes; (void)n_in; (void)out_size;
    const float* x     = (const float*)d_in[0];
    const float* W1    = (const float*)d_in[1];
    const float* b1    = (const float*)d_in[2];
    const float* gamma = (const float*)d_in[3];
    const float* beta  = (const float*)d_in[4];
    const float* W2    = (const float*)d_in[5];
    const float* b2    = (const float*)d_in[6];
    float* out = (float*)d_out;

    static int smem_set = 0;
    if (!smem_set) {
        cudaFuncSetAttribute(gemm1_mma, cudaFuncAttributeMaxDynamicSharedMemorySize,
                             SMEM_TOTAL);
        smem_set = 1;
    }

    pack_all<<<2052, 256>>>(W1, W2);
    gemm1_mma<<<B / 128, 256, SMEM_TOTAL>>>(x, b1);
    xcs_reduce<<<DIN / 64, 256>>>();
    bn_finish<<<H, 256>>>(gamma, beta);
    head<<<B / 8, 256>>>(x, b1, b2, out);
}

// round 11
// speedup vs baseline: 2.6643x; 1.0094x over previous
#include <cuda_runtime.h>
#include <cuda_fp16.h>
#include <cstdint>

#define B    32768
#define DIN  4096
#define H    100
#define DOUT 1000
#define BN_EPS 1e-4f

#define KC      64
#define NCHUNK  (DIN / KC)         // 64
#define NPAD    128
#define NG      13                 // n8 groups (N=104)

#define PITCH_B   144
#define SPLIT_SZ  (128 * PITCH_B)  // 18432
#define BUF_SZ    (2 * SPLIT_SZ)   // A-hi + B = 36864
#define B_OFF     SPLIT_SZ
#define SB1_OFF   (2 * BUF_SZ)     // 73728
#define XRED_OFF  (SB1_OFF + 512)  // 74240, two 4KB buffers
#define SMEM_TOTAL (XRED_OFF + 8192)

// ---- scratch ----
__device__ float     g_h[(size_t)B * H];
__device__ float     g_scale[H];
__device__ float     g_shift[H];
__device__ unsigned  g_w2p[DOUT * 4];
__device__ __half    g_w1h[(size_t)NPAD * DIN];
__device__ float     g_part[256 * 200];
__device__ float     g_xcs[256 * DIN];
__device__ float     g_xcolsum[DIN];

// ============================================================
// helpers
// ============================================================
__device__ __forceinline__ uint32_t smem_u32(const void* p) {
    uint32_t a;
    asm("{ .reg .u64 t; cvta.to.shared.u64 t, %1; cvt.u32.u64 %0, t; }"
        : "=r"(a) : "l"(p));
    return a;
}
__device__ __forceinline__ void ldsm4(uint32_t* r, uint32_t addr) {
    asm volatile("ldmatrix.sync.aligned.m8n8.x4.shared.b16 {%0,%1,%2,%3}, [%4];"
                 : "=r"(r[0]), "=r"(r[1]), "=r"(r[2]), "=r"(r[3]) : "r"(addr));
}
__device__ __forceinline__ void ldsm2(uint32_t* r, uint32_t addr) {
    asm volatile("ldmatrix.sync.aligned.m8n8.x2.shared.b16 {%0,%1}, [%2];"
                 : "=r"(r[0]), "=r"(r[1]) : "r"(addr));
}
__device__ __forceinline__ void mma16816(float* d, const uint32_t* a,
                                         const uint32_t* b) {
    asm volatile(
        "mma.sync.aligned.m16n8k16.row.col.f32.f16.f16.f32 "
        "{%0,%1,%2,%3}, {%4,%5,%6,%7}, {%8,%9}, {%0,%1,%2,%3};"
        : "+f"(d[0]), "+f"(d[1]), "+f"(d[2]), "+f"(d[3])
        : "r"(a[0]), "r"(a[1]), "r"(a[2]), "r"(a[3]), "r"(b[0]), "r"(b[1]));
}
__device__ __forceinline__ void cp16(uint32_t saddr, const void* g) {
    asm volatile("cp.async.cg.shared.global [%0], [%1], 16;"
                 :: "r"(saddr), "l"(g) : "memory");
}
#define CP_COMMIT() asm volatile("cp.async.commit_group;" ::: "memory")
#define CP_WAIT0()  asm volatile("cp.async.wait_group 0;"  ::: "memory")

__device__ __forceinline__ uint2 hipack(float4 v, float4& lo) {
    __half2 a = __floats2half2_rn(v.x, v.y);
    __half2 b = __floats2half2_rn(v.z, v.w);
    float2 fa = __half22float2(a), fb = __half22float2(b);
    lo.x = v.x - fa.x; lo.y = v.y - fa.y;
    lo.z = v.z - fb.x; lo.w = v.w - fb.y;
    return make_uint2(*(uint32_t*)&a, *(uint32_t*)&b);
}

// ============================================================
// Kernel P: pack sign(W1)->fp16 and sign(W2)->bitmask
// ============================================================
__global__ void pack_all(const float* __restrict__ W1,
                         const float* __restrict__ W2) {
    int gb = blockIdx.x, tid = threadIdx.x;
    if (gb < 2048) {
        int idx = gb * 256 + tid;
        int row = idx >> 12, col = idx & 4095;
        float v = 0.f;
        if (row < H) v = (W1[(size_t)row * DIN + col] >= 0.f) ? 1.f : -1.f;
        g_w1h[(size_t)row * DIN + col] = __float2half(v);
    } else {
        int j = (gb - 2048) * 256 + tid;
        if (j >= DOUT) return;
        unsigned w0 = 0, w1 = 0, w2 = 0, w3 = 0;
        const float* r = W2 + (size_t)j * H;
        #pragma unroll 4
        for (int k = 0; k < 32; k++)  if (r[k]      >= 0.f) w0 |= (1u << k);
        #pragma unroll 4
        for (int k = 0; k < 32; k++)  if (r[32 + k] >= 0.f) w1 |= (1u << k);
        #pragma unroll 4
        for (int k = 0; k < 32; k++)  if (r[64 + k] >= 0.f) w2 |= (1u << k);
        #pragma unroll
        for (int k = 0; k < 4;  k++)  if (r[96 + k] >= 0.f) w3 |= (1u << k);
        g_w2p[j * 4 + 0] = w0; g_w2p[j * 4 + 1] = w1;
        g_w2p[j * 4 + 2] = w2; g_w2p[j * 4 + 3] = w3;
    }
}

// ============================================================
// Kernel G: gemm1 hi-only fp16 MMA, 2 CTAs/SM, no reg-prefetch
// ============================================================
__global__ void __launch_bounds__(256, 2)
gemm1_mma(const float* __restrict__ x, const float* __restrict__ b1) {
    extern __shared__ char smem[];
    const uint32_t sm_base = smem_u32(smem);
    const int tid  = threadIdx.x;
    const int warp = tid >> 5;
    const int lane = tid & 31;
    const int row0 = blockIdx.x * 128;

    float* sb1 = (float*)(smem + SB1_OFF);
    if (tid < 104) sb1[tid] = (tid < H) ? b1[tid] : 0.f;

    // ---- prologue: stage chunk 0 into buf 0 ----
    {
        #pragma unroll
        for (int i = 0; i < 4; i++) {
            int idx = tid + i * 256;
            int r = idx >> 3, q = idx & 7;
            cp16(sm_base + B_OFF + (uint32_t)(r * PITCH_B + q * 16),
                 (const char*)g_w1h + (size_t)r * (DIN * 2) + q * 16);
        }
        CP_COMMIT();
        const float* xp = x + (size_t)row0 * DIN;
        float cs0 = 0.f, cs1 = 0.f, cs2 = 0.f, cs3 = 0.f;
        #pragma unroll
        for (int i = 0; i < 8; i++) {
            int idx = tid + i * 256;
            int r = idx >> 4, q = idx & 15;
            float4 v = __ldg((const float4*)(xp + (size_t)r * DIN + q * 4));
            float4 lo;
            uint2 hi = hipack(v, lo);
            *(uint2*)(smem + r * PITCH_B + q * 8) = hi;
            cs0 += lo.x; cs1 += lo.y; cs2 += lo.z; cs3 += lo.w;
        }
        float* xw = (float*)(smem + XRED_OFF);
        *(float4*)&xw[tid * 4] = make_float4(cs0, cs1, cs2, cs3);
        CP_WAIT0();
    }
    __syncthreads();

    float acc[NG * 4];
    #pragma unroll
    for (int i = 0; i < NG * 4; i++) acc[i] = 0.f;

    const uint32_t a_loff = (uint32_t)((warp * 16 + (lane & 15)) * PITCH_B +
                                       ((lane >> 4) * 8) * 2);
    const uint32_t b_loff = (uint32_t)(((lane >> 4) * 8 + (lane & 7)) * PITCH_B +
                                       (((lane >> 3) & 1) * 8) * 2);

    for (int c = 0; c < NCHUNK; c++) {
        const int buf = c & 1;
        const uint32_t abase = sm_base + buf * BUF_SZ;
        const uint32_t nbase = sm_base + (buf ^ 1) * BUF_SZ;

        // ---- reduce xred (chunk c lo colsums) -> g_xcs ----
        if (tid < 64) {
            const float* xr = (const float*)(smem + XRED_OFF + (c & 1) * 4096);
            int q = tid >> 2, j = tid & 3;
            float sum = 0.f;
            #pragma unroll
            for (int m = 0; m < 16; m++) sum += xr[(q + 16 * m) * 4 + j];
            g_xcs[blockIdx.x * DIN + c * 64 + tid] = sum;
        }

        // ---- cp.async next B tile into buf^1 ----
        if (c < NCHUNK - 1) {
            const char* wp = (const char*)g_w1h + (size_t)(c + 1) * 128;
            #pragma unroll
            for (int i = 0; i < 4; i++) {
                int idx = tid + i * 256;
                int r = idx >> 3, q = idx & 7;
                cp16(nbase + B_OFF + (uint32_t)(r * PITCH_B + q * 16),
                     wp + (size_t)r * (DIN * 2) + q * 16);
            }
        }
        CP_COMMIT();

        // ---- compute chunk c ----
        #pragma unroll
        for (int ks = 0; ks < 4; ks++) {
            uint32_t bf[NG * 2];
            #pragma unroll
            for (int gp = 0; gp < 6; gp++)
                ldsm4(bf + 4 * gp, abase + B_OFF + gp * (16 * PITCH_B) +
                      b_loff + ks * 32);
            ldsm2(bf + 24, abase + B_OFF + (96 + (lane & 7)) * PITCH_B +
                  (((lane >> 3) & 1) * 8) * 2 + ks * 32);
            uint32_t a[4];
            ldsm4(a, abase + a_loff + ks * 32);
            #pragma unroll
            for (int g = 0; g < NG; g++)
                mma16816(acc + g * 4, a, bf + 2 * g);
        }

        // ---- load + convert + STS x(c+1) (transient regs) ----
        if (c < NCHUNK - 1) {
            const float* xp = x + (size_t)row0 * DIN + (c + 1) * KC;
            char* base = smem + (buf ^ 1) * BUF_SZ;
            float cs0 = 0.f, cs1 = 0.f, cs2 = 0.f, cs3 = 0.f;
            #pragma unroll
            for (int i = 0; i < 8; i++) {
                int idx = tid + i * 256;
                int r = idx >> 4, q = idx & 15;
                float4 v = __ldg((const float4*)(xp + (size_t)r * DIN + q * 4));
                float4 lo;
                uint2 hi = hipack(v, lo);
                *(uint2*)(base + r * PITCH_B + q * 8) = hi;
                cs0 += lo.x; cs1 += lo.y; cs2 += lo.z; cs3 += lo.w;
            }
            float* xw = (float*)(smem + XRED_OFF + ((c + 1) & 1) * 4096);
            *(float4*)&xw[tid * 4] = make_float4(cs0, cs1, cs2, cs3);
        }
        CP_WAIT0();
        __syncthreads();
    }

    // ---- epilogue: h_hi + b1 ----
    const int gr = row0 + warp * 16 + (lane >> 2);
    const int cb = (lane & 3) * 2;
    #pragma unroll
    for (int g = 0; g < NG; g++) {
        int c0 = g * 8 + cb;
        if (c0 < H) {
            float2 lo, hi;
            lo.x = acc[g*4+0] + sb1[c0];
            lo.y = acc[g*4+1] + sb1[c0 + 1];
            hi.x = acc[g*4+2] + sb1[c0];
            hi.y = acc[g*4+3] + sb1[c0 + 1];
            *(float2*)(g_h + (size_t)gr * H + c0)       = lo;
            *(float2*)(g_h + (size_t)(gr + 8) * H + c0) = hi;
        }
    }

    // ---- fused BN pass 1 ----
    __threadfence_block();
    __syncthreads();
    float s = 0.f, s2 = 0.f;
    if (tid < 200) {
        int f = tid % 100;
        for (int rr = tid / 100; rr < 128; rr += 2) {
            float v = g_h[(size_t)(row0 + rr) * H + f];
            s += v;
            s2 = fmaf(v, v, s2);
        }
    }
    float* red = (float*)smem;
    if (tid < 200) { red[tid] = s; red[256 + tid] = s2; }
    __syncthreads();
    if (tid < 100) {
        g_part[blockIdx.x * 200 + tid]       = red[tid] + red[tid + 100];
        g_part[blockIdx.x * 200 + 100 + tid] = red[256 + tid] + red[356 + tid];
    }
}

// ============================================================
// Kernel R: reduce per-CTA lo colsums -> g_xcolsum (4-way c-split)
// ============================================================
__global__ void xcs_reduce() {
    __shared__ float sm[256];
    int kk = threadIdx.x & 63, cg = threadIdx.x >> 6;
    int k = blockIdx.x * 64 + kk;
    float s = 0.f;
    for (int c = cg * 64; c < cg * 64 + 64; c++) s += g_xcs[c * DIN + k];
    sm[threadIdx.x] = s;
    __syncthreads();
    if (cg == 0)
        g_xcolsum[k] = sm[kk] + sm[64 + kk] + sm[128 + kk] + sm[192 + kk];
}

// ============================================================
// Kernel S: bn_finish — 256 threads/feature, exact mu
// ============================================================
__global__ void bn_finish(const float* __restrict__ gamma,
                          const float* __restrict__ beta) {
    __shared__ float rs[256], rs2[256], rd[256];
    const int f   = blockIdx.x;
    const int tid = threadIdx.x;

    float s  = g_part[tid * 200 + f];
    float s2 = g_part[tid * 200 + 100 + f];

    float d = 0.f;
    const __half* wr = g_w1h + (size_t)f * DIN;
    #pragma unroll
    for (int t = 0; t < 16; t++) {
        int k = tid + 256 * t;
        d = fmaf(g_xcolsum[k], __half2float(wr[k]), d);
    }
    rs[tid] = s; rs2[tid] = s2; rd[tid] = d;
    __syncthreads();
    #pragma unroll
    for (int off = 128; off > 0; off >>= 1) {
        if (tid < off) {
            rs[tid]  += rs[tid + off];
            rs2[tid] += rs2[tid + off];
            rd[tid]  += rd[tid + off];
        }
        __syncthreads();
    }
    if (tid == 0) {
        float mu_hi = rs[0] * (1.f / B);
        float mu    = mu_hi + rd[0] * (1.f / B);
        float m2    = rs2[0] * (1.f / B);
        float var   = m2 - mu_hi * mu_hi;
        float sc    = gamma[f] * rsqrtf(var + BN_EPS);
        g_scale[f] = sc;
        g_shift[f] = fmaf(-mu, sc, beta[f]);
    }
}

// ============================================================
// Kernel H: head — fixup fused before ballots
// ============================================================
__global__ __launch_bounds__(256)
void head(const float* __restrict__ x, const float* __restrict__ b1,
          const float* __restrict__ b2, float* __restrict__ out) {
    __shared__ unsigned sw[DOUT * 4];
    __shared__ float    sb[DOUT];
    __shared__ float    ssc[H], ssh[H], sb1s[H];

    const int tid = threadIdx.x;
    for (int i = tid; i < DOUT * 4; i += 256) sw[i] = g_w2p[i];
    for (int i = tid; i < DOUT;     i += 256) sb[i] = b2[i];
    if (tid < H) { ssc[tid] = g_scale[tid]; ssh[tid] = g_shift[tid];
                   sb1s[tid] = b1[tid]; }
    __syncthreads();

    const int lane = tid & 31;
    const int warp = tid >> 5;
    const int row  = blockIdx.x * 8 + warp;

    const float* hr = g_h + (size_t)row * H;
    const float* xr = x + (size_t)row * DIN;

    float hn0 = fmaf(hr[lane],      ssc[lane],      ssh[lane]);
    float hn1 = fmaf(hr[32 + lane], ssc[32 + lane], ssh[32 + lane]);
    float hn2 = fmaf(hr[64 + lane], ssc[64 + lane], ssh[64 + lane]);
    float hn3 = (lane < 4) ?
                fmaf(hr[96 + lane], ssc[96 + lane], ssh[96 + lane]) : -1.f;

    #pragma unroll
    for (int grp = 0; grp < 4; grp++) {
        float hn = (grp == 0) ? hn0 : (grp == 1) ? hn1 : (grp == 2) ? hn2 : hn3;
        bool flag = (grp < 3 || lane < 4) &&
                    (fabsf(hn) < 0.12f * fabsf(ssc[(grp * 32 + lane) % H]));
        unsigned m = __ballot_sync(0xffffffffu, flag);
        while (m) {
            int bpos = __ffs(m) - 1;
            m &= m - 1;
            int feat = grp * 32 + bpos;
            const __half* wr = g_w1h + (size_t)feat * DIN;
            float s = 0.f, comp = 0.f;
            #pragma unroll 4
            for (int t = 0; t < 128; t++) {
                int k = lane + 32 * t;
                float term = xr[k] * __half2float(wr[k]);
                float y  = __fsub_rn(term, comp);
                float t2 = __fadd_rn(s, y);
                comp = __fsub_rn(__fsub_rn(t2, s), y);
                s = t2;
            }
            s = __fadd_rn(s, comp);
            #pragma unroll
            for (int off = 16; off > 0; off >>= 1)
                s += __shfl_xor_sync(0xffffffffu, s, off);
            if (lane == bpos) {
                float fix = fmaf(s + sb1s[feat], ssc[feat], ssh[feat]);
                if (grp == 0) hn0 = fix;
                else if (grp == 1) hn1 = fix;
                else if (grp == 2) hn2 = fix;
                else hn3 = fix;
            }
        }
    }

    unsigned a0 = __ballot_sync(0xffffffffu, hn0 >= 0.f);
    unsigned a1 = __ballot_sync(0xffffffffu, hn1 >= 0.f);
    unsigned a2 = __ballot_sync(0xffffffffu, hn2 >= 0.f);
    unsigned a3 = __ballot_sync(0xffffffffu, (lane < 4) && (hn3 >= 0.f));

    float o[32];
    float mx = -1e30f;
    #pragma unroll
    for (int i = 0; i < 32; i++) {
        int j = i * 32 + lane;
        if (j < DOUT) {
            uint4 w = *(const uint4*)&sw[j * 4];
            int p = __popc(a0 ^ w.x) + __popc(a1 ^ w.y) +
                    __popc(a2 ^ w.z) + __popc(a3 ^ w.w);
            o[i] = (float)(H - 2 * p) + sb[j];
            mx = fmaxf(mx, o[i]);
        } else {
            o[i] = -1e30f;
        }
    }
    #pragma unroll
    for (int off = 16; off > 0; off >>= 1)
        mx = fmaxf(mx, __shfl_xor_sync(0xffffffffu, mx, off));

    float s = 0.f;
    #pragma unroll
    for (int i = 0; i < 32; i++)
        s += exp2f((o[i] - mx) * 1.4426950408889634f);
    #pragma unroll
    for (int off = 16; off > 0; off >>= 1)
        s += __shfl_xor_sync(0xffffffffu, s, off);

    float lse = fmaf(0.69314718055994531f, __log2f(s), mx);

    float* orow = out + (size_t)row * DOUT;
    #pragma unroll
    for (int i = 0; i < 32; i++) {
        int j = i * 32 + lane;
        if (j < DOUT) orow[j] = o[i] - lse;
    }
}

// ============================================================
// Launch
// ============================================================
extern "C" void kernel_launch(void* const* d_in, const int* in_sizes, int n_in,
                              void* d_out, int out_size) {
    (void)in_sizes; (void)n_in; (void)out_size;
    const float* x     = (const float*)d_in[0];
    const float* W1    = (const float*)d_in[1];
    const float* b1    = (const float*)d_in[2];
    const float* gamma = (const float*)d_in[3];
    const float* beta  = (const float*)d_in[4];
    const float* W2    = (const float*)d_in[5];
    const float* b2    = (const float*)d_in[6];
    float* out = (float*)d_out;

    static int smem_set = 0;
    if (!smem_set) {
        cudaFuncSetAttribute(gemm1_mma, cudaFuncAttributeMaxDynamicSharedMemorySize,
                             SMEM_TOTAL);
        smem_set = 1;
    }

    pack_all<<<2052, 256>>>(W1, W2);
    gemm1_mma<<<B / 128, 256, SMEM_TOTAL>>>(x, b1);
    xcs_reduce<<<DIN / 64, 256>>>();
    bn_finish<<<H, 256>>>(gamma, beta);
    head<<<B / 8, 256>>>(x, b1, b2, out);
}

// round 12
// speedup vs baseline: 2.8007x; 1.0512x over previous
#include <cuda_runtime.h>
#include <cuda_fp16.h>
#include <cstdint>

#define B    32768
#define DIN  4096
#define H    100
#define DOUT 1000
#define BN_EPS 1e-4f

#define KC      64
#define NCHUNK  (DIN / KC)         // 64
#define NPAD    128
#define NG      13                 // n8 groups (N=104)

#define PITCH_B   144
#define SPLIT_SZ  (128 * PITCH_B)  // 18432
#define BUF_SZ    (2 * SPLIT_SZ)   // A-hi + B = 36864
#define B_OFF     SPLIT_SZ
#define SB1_OFF   (2 * BUF_SZ)     // 73728
#define XRED_OFF  (SB1_OFF + 512)  // 74240, two 4KB buffers
#define SMEM_TOTAL (XRED_OFF + 8192)

// ---- scratch ----
__device__ float     g_h[(size_t)B * H];
__device__ float     g_scale[H];
__device__ float     g_shift[H];
__device__ unsigned  g_w2p[DOUT * 4];
__device__ __half    g_w1h[(size_t)NPAD * DIN];
__device__ float     g_part[256 * 200];
__device__ float     g_xcs[256 * DIN];
__device__ float     g_xcolsum[DIN];

// ============================================================
// helpers
// ============================================================
__device__ __forceinline__ uint32_t smem_u32(const void* p) {
    uint32_t a;
    asm("{ .reg .u64 t; cvta.to.shared.u64 t, %1; cvt.u32.u64 %0, t; }"
        : "=r"(a) : "l"(p));
    return a;
}
__device__ __forceinline__ void ldsm4(uint32_t* r, uint32_t addr) {
    asm volatile("ldmatrix.sync.aligned.m8n8.x4.shared.b16 {%0,%1,%2,%3}, [%4];"
                 : "=r"(r[0]), "=r"(r[1]), "=r"(r[2]), "=r"(r[3]) : "r"(addr));
}
__device__ __forceinline__ void ldsm2(uint32_t* r, uint32_t addr) {
    asm volatile("ldmatrix.sync.aligned.m8n8.x2.shared.b16 {%0,%1}, [%2];"
                 : "=r"(r[0]), "=r"(r[1]) : "r"(addr));
}
__device__ __forceinline__ void mma16816(float* d, const uint32_t* a,
                                         const uint32_t* b) {
    asm volatile(
        "mma.sync.aligned.m16n8k16.row.col.f32.f16.f16.f32 "
        "{%0,%1,%2,%3}, {%4,%5,%6,%7}, {%8,%9}, {%0,%1,%2,%3};"
        : "+f"(d[0]), "+f"(d[1]), "+f"(d[2]), "+f"(d[3])
        : "r"(a[0]), "r"(a[1]), "r"(a[2]), "r"(a[3]), "r"(b[0]), "r"(b[1]));
}
__device__ __forceinline__ void cp16(uint32_t saddr, const void* g) {
    asm volatile("cp.async.cg.shared.global [%0], [%1], 16;"
                 :: "r"(saddr), "l"(g) : "memory");
}
#define CP_COMMIT() asm volatile("cp.async.commit_group;" ::: "memory")
#define CP_WAIT0()  asm volatile("cp.async.wait_group 0;"  ::: "memory")

__device__ __forceinline__ uint2 hipack(float4 v, float4& lo) {
    __half2 a = __floats2half2_rn(v.x, v.y);
    __half2 b = __floats2half2_rn(v.z, v.w);
    float2 fa = __half22float2(a), fb = __half22float2(b);
    lo.x = v.x - fa.x; lo.y = v.y - fa.y;
    lo.z = v.z - fb.x; lo.w = v.w - fb.y;
    return make_uint2(*(uint32_t*)&a, *(uint32_t*)&b);
}
__device__ __forceinline__ int sx8(uint32_t pk, int q) {
    return (int)(signed char)((pk >> (8 * q)) & 0xffu);
}

// ============================================================
// Kernel P: pack sign(W1)->fp16 (vectorized) and sign(W2)->bitmask
// ============================================================
__global__ void pack_all(const float* __restrict__ W1,
                         const float* __restrict__ W2) {
    int gb = blockIdx.x, tid = threadIdx.x;
    if (gb < 512) {
        int e   = (gb * 256 + tid) * 4;        // element index, < 128*4096
        int row = e >> 12, col = e & 4095;
        __half2 h0 = __floats2half2_rn(0.f, 0.f), h1 = h0;
        if (row < H) {
            float4 v = *(const float4*)(W1 + (size_t)row * DIN + col);
            h0 = __floats2half2_rn((v.x >= 0.f) ? 1.f : -1.f,
                                   (v.y >= 0.f) ? 1.f : -1.f);
            h1 = __floats2half2_rn((v.z >= 0.f) ? 1.f : -1.f,
                                   (v.w >= 0.f) ? 1.f : -1.f);
        }
        *(uint2*)((char*)g_w1h + (size_t)e * 2) =
            make_uint2(*(uint32_t*)&h0, *(uint32_t*)&h1);
    } else {
        int j = (gb - 512) * 256 + tid;
        if (j >= DOUT) return;
        unsigned w0 = 0, w1 = 0, w2 = 0, w3 = 0;
        const float* r = W2 + (size_t)j * H;
        #pragma unroll 4
        for (int k = 0; k < 32; k++)  if (r[k]      >= 0.f) w0 |= (1u << k);
        #pragma unroll 4
        for (int k = 0; k < 32; k++)  if (r[32 + k] >= 0.f) w1 |= (1u << k);
        #pragma unroll 4
        for (int k = 0; k < 32; k++)  if (r[64 + k] >= 0.f) w2 |= (1u << k);
        #pragma unroll
        for (int k = 0; k < 4;  k++)  if (r[96 + k] >= 0.f) w3 |= (1u << k);
        g_w2p[j * 4 + 0] = w0; g_w2p[j * 4 + 1] = w1;
        g_w2p[j * 4 + 2] = w2; g_w2p[j * 4 + 3] = w3;
    }
}

// ============================================================
// Kernel G: gemm1 hi-only fp16 MMA, 2 CTAs/SM (R11 measured)
// ============================================================
__global__ void __launch_bounds__(256, 2)
gemm1_mma(const float* __restrict__ x, const float* __restrict__ b1) {
    extern __shared__ char smem[];
    const uint32_t sm_base = smem_u32(smem);
    const int tid  = threadIdx.x;
    const int warp = tid >> 5;
    const int lane = tid & 31;
    const int row0 = blockIdx.x * 128;

    float* sb1 = (float*)(smem + SB1_OFF);
    if (tid < 104) sb1[tid] = (tid < H) ? b1[tid] : 0.f;

    {
        #pragma unroll
        for (int i = 0; i < 4; i++) {
            int idx = tid + i * 256;
            int r = idx >> 3, q = idx & 7;
            cp16(sm_base + B_OFF + (uint32_t)(r * PITCH_B + q * 16),
                 (const char*)g_w1h + (size_t)r * (DIN * 2) + q * 16);
        }
        CP_COMMIT();
        const float* xp = x + (size_t)row0 * DIN;
        float cs0 = 0.f, cs1 = 0.f, cs2 = 0.f, cs3 = 0.f;
        #pragma unroll
        for (int i = 0; i < 8; i++) {
            int idx = tid + i * 256;
            int r = idx >> 4, q = idx & 15;
            float4 v = __ldg((const float4*)(xp + (size_t)r * DIN + q * 4));
            float4 lo;
            uint2 hi = hipack(v, lo);
            *(uint2*)(smem + r * PITCH_B + q * 8) = hi;
            cs0 += lo.x; cs1 += lo.y; cs2 += lo.z; cs3 += lo.w;
        }
        float* xw = (float*)(smem + XRED_OFF);
        *(float4*)&xw[tid * 4] = make_float4(cs0, cs1, cs2, cs3);
        CP_WAIT0();
    }
    __syncthreads();

    float acc[NG * 4];
    #pragma unroll
    for (int i = 0; i < NG * 4; i++) acc[i] = 0.f;

    const uint32_t a_loff = (uint32_t)((warp * 16 + (lane & 15)) * PITCH_B +
                                       ((lane >> 4) * 8) * 2);
    const uint32_t b_loff = (uint32_t)(((lane >> 4) * 8 + (lane & 7)) * PITCH_B +
                                       (((lane >> 3) & 1) * 8) * 2);

    for (int c = 0; c < NCHUNK; c++) {
        const int buf = c & 1;
        const uint32_t abase = sm_base + buf * BUF_SZ;
        const uint32_t nbase = sm_base + (buf ^ 1) * BUF_SZ;

        if (tid < 64) {
            const float* xr = (const float*)(smem + XRED_OFF + (c & 1) * 4096);
            int q = tid >> 2, j = tid & 3;
            float sum = 0.f;
            #pragma unroll
            for (int m = 0; m < 16; m++) sum += xr[(q + 16 * m) * 4 + j];
            g_xcs[blockIdx.x * DIN + c * 64 + tid] = sum;
        }

        if (c < NCHUNK - 1) {
            const char* wp = (const char*)g_w1h + (size_t)(c + 1) * 128;
            #pragma unroll
            for (int i = 0; i < 4; i++) {
                int idx = tid + i * 256;
                int r = idx >> 3, q = idx & 7;
                cp16(nbase + B_OFF + (uint32_t)(r * PITCH_B + q * 16),
                     wp + (size_t)r * (DIN * 2) + q * 16);
            }
        }
        CP_COMMIT();

        #pragma unroll
        for (int ks = 0; ks < 4; ks++) {
            uint32_t bf[NG * 2];
            #pragma unroll
            for (int gp = 0; gp < 6; gp++)
                ldsm4(bf + 4 * gp, abase + B_OFF + gp * (16 * PITCH_B) +
                      b_loff + ks * 32);
            ldsm2(bf + 24, abase + B_OFF + (96 + (lane & 7)) * PITCH_B +
                  (((lane >> 3) & 1) * 8) * 2 + ks * 32);
            uint32_t a[4];
            ldsm4(a, abase + a_loff + ks * 32);
            #pragma unroll
            for (int g = 0; g < NG; g++)
                mma16816(acc + g * 4, a, bf + 2 * g);
        }

        if (c < NCHUNK - 1) {
            const float* xp = x + (size_t)row0 * DIN + (c + 1) * KC;
            char* base = smem + (buf ^ 1) * BUF_SZ;
            float cs0 = 0.f, cs1 = 0.f, cs2 = 0.f, cs3 = 0.f;
            #pragma unroll
            for (int i = 0; i < 8; i++) {
                int idx = tid + i * 256;
                int r = idx >> 4, q = idx & 15;
                float4 v = __ldg((const float4*)(xp + (size_t)r * DIN + q * 4));
                float4 lo;
                uint2 hi = hipack(v, lo);
                *(uint2*)(base + r * PITCH_B + q * 8) = hi;
                cs0 += lo.x; cs1 += lo.y; cs2 += lo.z; cs3 += lo.w;
            }
            float* xw = (float*)(smem + XRED_OFF + ((c + 1) & 1) * 4096);
            *(float4*)&xw[tid * 4] = make_float4(cs0, cs1, cs2, cs3);
        }
        CP_WAIT0();
        __syncthreads();
    }

    const int gr = row0 + warp * 16 + (lane >> 2);
    const int cb = (lane & 3) * 2;
    #pragma unroll
    for (int g = 0; g < NG; g++) {
        int c0 = g * 8 + cb;
        if (c0 < H) {
            float2 lo, hi;
            lo.x = acc[g*4+0] + sb1[c0];
            lo.y = acc[g*4+1] + sb1[c0 + 1];
            hi.x = acc[g*4+2] + sb1[c0];
            hi.y = acc[g*4+3] + sb1[c0 + 1];
            *(float2*)(g_h + (size_t)gr * H + c0)       = lo;
            *(float2*)(g_h + (size_t)(gr + 8) * H + c0) = hi;
        }
    }

    __threadfence_block();
    __syncthreads();
    float s = 0.f, s2 = 0.f;
    if (tid < 200) {
        int f = tid % 100;
        for (int rr = tid / 100; rr < 128; rr += 2) {
            float v = g_h[(size_t)(row0 + rr) * H + f];
            s += v;
            s2 = fmaf(v, v, s2);
        }
    }
    float* red = (float*)smem;
    if (tid < 200) { red[tid] = s; red[256 + tid] = s2; }
    __syncthreads();
    if (tid < 100) {
        g_part[blockIdx.x * 200 + tid]       = red[tid] + red[tid + 100];
        g_part[blockIdx.x * 200 + 100 + tid] = red[256 + tid] + red[356 + tid];
    }
}

// ============================================================
// Kernel R: reduce per-CTA lo colsums -> g_xcolsum
// ============================================================
__global__ void xcs_reduce() {
    __shared__ float sm[256];
    int kk = threadIdx.x & 63, cg = threadIdx.x >> 6;
    int k = blockIdx.x * 64 + kk;
    float s = 0.f;
    for (int c = cg * 64; c < cg * 64 + 64; c++) s += g_xcs[c * DIN + k];
    sm[threadIdx.x] = s;
    __syncthreads();
    if (cg == 0)
        g_xcolsum[k] = sm[kk] + sm[64 + kk] + sm[128 + kk] + sm[192 + kk];
}

// ============================================================
// Kernel S: bn_finish — 256 threads/feature, exact mu
// ============================================================
__global__ void bn_finish(const float* __restrict__ gamma,
                          const float* __restrict__ beta) {
    __shared__ float rs[256], rs2[256], rd[256];
    const int f   = blockIdx.x;
    const int tid = threadIdx.x;

    float s  = g_part[tid * 200 + f];
    float s2 = g_part[tid * 200 + 100 + f];

    float d = 0.f;
    const __half* wr = g_w1h + (size_t)f * DIN;
    #pragma unroll
    for (int t = 0; t < 16; t++) {
        int k = tid + 256 * t;
        d = fmaf(g_xcolsum[k], __half2float(wr[k]), d);
    }
    rs[tid] = s; rs2[tid] = s2; rd[tid] = d;
    __syncthreads();
    #pragma unroll
    for (int off = 128; off > 0; off >>= 1) {
        if (tid < off) {
            rs[tid]  += rs[tid + off];
            rs2[tid] += rs2[tid + off];
            rd[tid]  += rd[tid + off];
        }
        __syncthreads();
    }
    if (tid == 0) {
        float mu_hi = rs[0] * (1.f / B);
        float mu    = mu_hi + rd[0] * (1.f / B);
        float m2    = rs2[0] * (1.f / B);
        float var   = m2 - mu_hi * mu_hi;
        float sc    = gamma[f] * rsqrtf(var + BN_EPS);
        g_scale[f] = sc;
        g_shift[f] = fmaf(-mu, sc, beta[f]);
    }
}

// ============================================================
// Kernel H: head — byte-packed logits (exact ints), fixup fused,
// low-register / high-occupancy variant
// ============================================================
#define LOG2E 1.4426950408889634f
#define LN2   0.69314718055994531f

__global__ __launch_bounds__(256, 4)
void head(const float* __restrict__ x, const float* __restrict__ b1,
          const float* __restrict__ b2, float* __restrict__ out) {
    __shared__ uint4 sw4[DOUT];
    __shared__ float sb[DOUT];
    __shared__ float ssc[H], ssh[H], sb1s[H];

    const int tid = threadIdx.x;
    for (int i = tid; i < DOUT; i += 256) {
        sw4[i] = ((const uint4*)g_w2p)[i];
        sb[i]  = b2[i];
    }
    if (tid < H) { ssc[tid] = g_scale[tid]; ssh[tid] = g_shift[tid];
                   sb1s[tid] = b1[tid]; }
    __syncthreads();

    const int lane = tid & 31;
    const int warp = tid >> 5;
    const int row  = blockIdx.x * 8 + warp;

    const float* hr = g_h + (size_t)row * H;
    const float* xr = x + (size_t)row * DIN;

    float hn0 = fmaf(hr[lane],      ssc[lane],      ssh[lane]);
    float hn1 = fmaf(hr[32 + lane], ssc[32 + lane], ssh[32 + lane]);
    float hn2 = fmaf(hr[64 + lane], ssc[64 + lane], ssh[64 + lane]);
    float hn3 = (lane < 4) ?
                fmaf(hr[96 + lane], ssc[96 + lane], ssh[96 + lane]) : -1.f;

    // ---- inline exact fixup of boundary entries ----
    #pragma unroll
    for (int grp = 0; grp < 4; grp++) {
        float hn = (grp == 0) ? hn0 : (grp == 1) ? hn1 : (grp == 2) ? hn2 : hn3;
        bool flag = (grp < 3 || lane < 4) &&
                    (fabsf(hn) < 0.12f * fabsf(ssc[(grp * 32 + lane) % H]));
        unsigned m = __ballot_sync(0xffffffffu, flag);
        while (m) {
            int bpos = __ffs(m) - 1;
            m &= m - 1;
            int feat = grp * 32 + bpos;
            const __half* wr = g_w1h + (size_t)feat * DIN;
            float s = 0.f, comp = 0.f;
            #pragma unroll 4
            for (int t = 0; t < 128; t++) {
                int k = lane + 32 * t;
                float term = xr[k] * __half2float(wr[k]);
                float y  = __fsub_rn(term, comp);
                float t2 = __fadd_rn(s, y);
                comp = __fsub_rn(__fsub_rn(t2, s), y);
                s = t2;
            }
            s = __fadd_rn(s, comp);
            #pragma unroll
            for (int off = 16; off > 0; off >>= 1)
                s += __shfl_xor_sync(0xffffffffu, s, off);
            if (lane == bpos) {
                float fix = fmaf(s + sb1s[feat], ssc[feat], ssh[feat]);
                if (grp == 0) hn0 = fix;
                else if (grp == 1) hn1 = fix;
                else if (grp == 2) hn2 = fix;
                else hn3 = fix;
            }
        }
    }

    unsigned a0 = __ballot_sync(0xffffffffu, hn0 >= 0.f);
    unsigned a1 = __ballot_sync(0xffffffffu, hn1 >= 0.f);
    unsigned a2 = __ballot_sync(0xffffffffu, hn2 >= 0.f);
    unsigned a3 = __ballot_sync(0xffffffffu, (lane < 4) && (hn3 >= 0.f));

    // ---- pass A: popc -> packed int8 logits (exact), track max ----
    uint32_t pk[8];
    float mx = -1e30f;
    #pragma unroll
    for (int i = 0; i < 8; i++) {
        int jb = i * 128 + lane * 4;
        uint32_t p = 0;
        if (jb < DOUT) {
            float4 bias = *(const float4*)&sb[jb];
            #pragma unroll
            for (int q = 0; q < 4; q++) {
                uint4 w = sw4[jb + q];
                int pc = __popc(a0 ^ w.x) + __popc(a1 ^ w.y) +
                         __popc(a2 ^ w.z) + __popc(a3 ^ w.w);
                int v = H - 2 * pc;
                p |= (uint32_t)(v & 255) << (8 * q);
                float bi = (q == 0) ? bias.x : (q == 1) ? bias.y :
                           (q == 2) ? bias.z : bias.w;
                mx = fmaxf(mx, (float)v + bi);
            }
        }
        pk[i] = p;
    }
    #pragma unroll
    for (int off = 16; off > 0; off >>= 1)
        mx = fmaxf(mx, __shfl_xor_sync(0xffffffffu, mx, off));

    // ---- pass B: sum exp ----
    float s = 0.f;
    #pragma unroll
    for (int i = 0; i < 8; i++) {
        int jb = i * 128 + lane * 4;
        if (jb < DOUT) {
            float4 bias = *(const float4*)&sb[jb];
            s += exp2f(((float)sx8(pk[i], 0) + bias.x - mx) * LOG2E);
            s += exp2f(((float)sx8(pk[i], 1) + bias.y - mx) * LOG2E);
            s += exp2f(((float)sx8(pk[i], 2) + bias.z - mx) * LOG2E);
            s += exp2f(((float)sx8(pk[i], 3) + bias.w - mx) * LOG2E);
        }
    }
    #pragma unroll
    for (int off = 16; off > 0; off >>= 1)
        s += __shfl_xor_sync(0xffffffffu, s, off);
    float lse = fmaf(LN2, __log2f(s), mx);

    // ---- pass C: store ----
    float* orow = out + (size_t)row * DOUT;
    #pragma unroll
    for (int i = 0; i < 8; i++) {
        int jb = i * 128 + lane * 4;
        if (jb < DOUT) {
            float4 bias = *(const float4*)&sb[jb];
            float4 v;
            v.x = (float)sx8(pk[i], 0) + bias.x - lse;
            v.y = (float)sx8(pk[i], 1) + bias.y - lse;
            v.z = (float)sx8(pk[i], 2) + bias.z - lse;
            v.w = (float)sx8(pk[i], 3) + bias.w - lse;
            *(float4*)(orow + jb) = v;
        }
    }
}

// ============================================================
// Launch
// ============================================================
extern "C" void kernel_launch(void* const* d_in, const int* in_sizes, int n_in,
                              void* d_out, int out_size) {
    (void)in_sizes; (void)n_in; (void)out_size;
    const float* x     = (const float*)d_in[0];
    const float* W1    = (const float*)d_in[1];
    const float* b1    = (const float*)d_in[2];
    const float* gamma = (const float*)d_in[3];
    const float* beta  = (const float*)d_in[4];
    const float* W2    = (const float*)d_in[5];
    const float* b2    = (const float*)d_in[6];
    float* out = (float*)d_out;

    static int smem_set = 0;
    if (!smem_set) {
        cudaFuncSetAttribute(gemm1_mma, cudaFuncAttributeMaxDynamicSharedMemorySize,
                             SMEM_TOTAL);
        smem_set = 1;
    }

    pack_all<<<516, 256>>>(W1, W2);
    gemm1_mma<<<B / 128, 256, SMEM_TOTAL>>>(x, b1);
    xcs_reduce<<<DIN / 64, 256>>>();
    bn_finish<<<H, 256>>>(gamma, beta);
    head<<<B / 8, 256>>>(x, b1, b2, out);
}